// round 1
// baseline (speedup 1.0000x reference)
#include <cuda_runtime.h>
#include <math.h>

// ---------------- problem constants ----------------
constexpr int HDIM  = 768;
constexpr int SEQL  = 512;
constexpr int NB    = 8;
constexpr int NLAYR = 12;
constexpr int NHEAD = 12;
constexpr int DHEAD = 64;
constexpr int FFDIM = 3072;
constexpr int MROWS = NB * SEQL;   // 4096
constexpr int NLAB  = 9;

// ---------------- device scratch (no allocations allowed) ----------------
__device__ float gX[MROWS * HDIM];
__device__ float gT[MROWS * HDIM];
__device__ float gQ[MROWS * HDIM];
__device__ float gK[MROWS * HDIM];
__device__ float gV[MROWS * HDIM];
__device__ float gCtx[MROWS * HDIM];
__device__ float gH1[MROWS * HDIM];
__device__ float gFF[MROWS * FFDIM];
__device__ float gScores[25165824];          // 8*12*512*512
__device__ float gFeats[MROWS * NLAB];
__device__ float gPart[NB];
__device__ int   gHist[(SEQL - 1) * NB * NLAB];
__device__ int   gTags[NB * SEQL];

// ---------------- block reduce ----------------
__device__ __forceinline__ float blockReduceSum(float v) {
    __shared__ float sh[32];
    int lane = threadIdx.x & 31, wid = threadIdx.x >> 5;
    #pragma unroll
    for (int o = 16; o > 0; o >>= 1) v += __shfl_down_sync(0xffffffffu, v, o);
    if (lane == 0) sh[wid] = v;
    __syncthreads();
    int nw = blockDim.x >> 5;
    v = (threadIdx.x < nw) ? sh[threadIdx.x] : 0.f;
    if (wid == 0) {
        #pragma unroll
        for (int o = 16; o > 0; o >>= 1) v += __shfl_down_sync(0xffffffffu, v, o);
    }
    if (threadIdx.x == 0) sh[0] = v;
    __syncthreads();
    float r = sh[0];
    __syncthreads();
    return r;
}

// ---------------- generic SGEMM ----------------
// C(MxN) = alpha * A(MxK) * B, B either KxN (TRANSB=false) or NxK (TRANSB=true).
// Epilogue: 0 none, 1 +bias, 2 +bias+residual, 3 +bias then exact GELU.
// Batched via blockIdx.z: offset = (z/zdiv)*sOut + (z%zdiv)*sIn per operand.
#define BM 128
#define BN 64
#define BKK 16
#define TM 8
#define TN 4

template<bool TRANSB, int EPI>
__global__ __launch_bounds__(256)
void sgemm_kernel(const float* __restrict__ A, int lda, long long sAo, long long sAi,
                  const float* __restrict__ B, int ldb, long long sBo, long long sBi,
                  float* __restrict__ C, int ldc, long long sCo, long long sCi,
                  const float* __restrict__ bias,
                  const float* __restrict__ resid, int ldr,
                  int M, int N, int K, float alpha, int zdiv)
{
    __shared__ float As[BKK][BM];
    __shared__ float Bs[BKK][BN];

    int z = blockIdx.z;
    int zo = z / zdiv, zi = z - zo * zdiv;
    A += zo * sAo + zi * sAi;
    B += zo * sBo + zi * sBi;
    C += zo * sCo + zi * sCi;

    int bm = blockIdx.y * BM, bn = blockIdx.x * BN;
    int tid = threadIdx.x;
    int tx = tid & 15, ty = tid >> 4;

    float acc[TM][TN];
    #pragma unroll
    for (int i = 0; i < TM; i++)
        #pragma unroll
        for (int j = 0; j < TN; j++) acc[i][j] = 0.f;

    for (int k0 = 0; k0 < K; k0 += BKK) {
        // Load A tile (BM x BKK), store transposed into As[k][m]
        {
            int row = tid >> 1;
            int col = (tid & 1) * 8;
            int gr = bm + row;
            #pragma unroll
            for (int i = 0; i < 8; i++) {
                int gc = k0 + col + i;
                float v = (gr < M && gc < K) ? A[(long long)gr * lda + gc] : 0.f;
                As[col + i][row] = v;
            }
        }
        if (!TRANSB) {
            int kk = tid >> 4;
            int nn = (tid & 15) * 4;
            int gk = k0 + kk;
            #pragma unroll
            for (int j = 0; j < 4; j++) {
                int gn = bn + nn + j;
                Bs[kk][nn + j] = (gk < K && gn < N) ? B[(long long)gk * ldb + gn] : 0.f;
            }
        } else {
            int nn = tid >> 2;
            int kk = (tid & 3) * 4;
            int gn = bn + nn;
            #pragma unroll
            for (int j = 0; j < 4; j++) {
                int gk = k0 + kk + j;
                Bs[kk + j][nn] = (gn < N && gk < K) ? B[(long long)gn * ldb + gk] : 0.f;
            }
        }
        __syncthreads();

        #pragma unroll
        for (int kk = 0; kk < BKK; kk++) {
            float a[TM], b[TN];
            #pragma unroll
            for (int i = 0; i < TM; i++) a[i] = As[kk][ty * TM + i];
            #pragma unroll
            for (int j = 0; j < TN; j++) b[j] = Bs[kk][tx * TN + j];
            #pragma unroll
            for (int i = 0; i < TM; i++)
                #pragma unroll
                for (int j = 0; j < TN; j++) acc[i][j] = fmaf(a[i], b[j], acc[i][j]);
        }
        __syncthreads();
    }

    #pragma unroll
    for (int i = 0; i < TM; i++) {
        int gm = bm + ty * TM + i;
        if (gm >= M) continue;
        #pragma unroll
        for (int j = 0; j < TN; j++) {
            int gn = bn + tx * TN + j;
            if (gn >= N) continue;
            float v = acc[i][j] * alpha;
            if (EPI >= 1) v += bias[gn];
            if (EPI == 2) v += resid[(long long)gm * ldr + gn];
            if (EPI == 3) v = 0.5f * v * (1.0f + erff(v * 0.70710678118654752f));
            C[(long long)gm * ldc + gn] = v;
        }
    }
}

// ---------------- embedding + LN ----------------
__global__ void embed_ln_kernel(const int* __restrict__ ids, const int* __restrict__ tts,
                                const float* __restrict__ we, const float* __restrict__ pe,
                                const float* __restrict__ te, const float* __restrict__ s,
                                const float* __restrict__ b, float* __restrict__ out)
{
    int n = blockIdx.x;
    int sp = n & (SEQL - 1);
    int id = ids[n];
    int tt = tts[n];
    float v[3];
    float sum = 0.f;
    #pragma unroll
    for (int i = 0; i < 3; i++) {
        int h = threadIdx.x + i * 256;
        v[i] = we[(long long)id * HDIM + h] + pe[sp * HDIM + h] + te[tt * HDIM + h];
        sum += v[i];
    }
    float mean = blockReduceSum(sum) * (1.f / HDIM);
    float vs = 0.f;
    #pragma unroll
    for (int i = 0; i < 3; i++) { float d = v[i] - mean; vs += d * d; }
    float var = blockReduceSum(vs) * (1.f / HDIM);
    float inv = rsqrtf(var + 1e-12f);
    #pragma unroll
    for (int i = 0; i < 3; i++) {
        int h = threadIdx.x + i * 256;
        out[(long long)n * HDIM + h] = (v[i] - mean) * inv * s[h] + b[h];
    }
}

// ---------------- layernorm over rows ----------------
__global__ void layernorm_kernel(const float* __restrict__ in, float* __restrict__ out,
                                 const float* __restrict__ s, const float* __restrict__ b)
{
    int n = blockIdx.x;
    const float* row = in + (long long)n * HDIM;
    float v[3];
    float sum = 0.f;
    #pragma unroll
    for (int i = 0; i < 3; i++) { v[i] = row[threadIdx.x + i * 256]; sum += v[i]; }
    float mean = blockReduceSum(sum) * (1.f / HDIM);
    float vs = 0.f;
    #pragma unroll
    for (int i = 0; i < 3; i++) { float d = v[i] - mean; vs += d * d; }
    float var = blockReduceSum(vs) * (1.f / HDIM);
    float inv = rsqrtf(var + 1e-12f);
    #pragma unroll
    for (int i = 0; i < 3; i++) {
        int h = threadIdx.x + i * 256;
        out[(long long)n * HDIM + h] = (v[i] - mean) * inv * s[h] + b[h];
    }
}

// ---------------- masked softmax over score rows ----------------
__global__ void softmax_kernel(float* __restrict__ sc, const int* __restrict__ amask)
{
    int q = blockIdx.x;         // 0..511
    int bh = blockIdx.y;        // 0..95
    int b = bh / NHEAD;
    float* row = sc + ((long long)bh * SEQL + q) * SEQL;
    const int* mrow = amask + b * SEQL;
    int t = threadIdx.x;        // 128
    float v[4];
    float mx = -1e30f;
    #pragma unroll
    for (int i = 0; i < 4; i++) {
        int k = t + i * 128;
        float bias = (mrow[k] > 0) ? 0.f : -10000.f;
        v[i] = row[k] + bias;
        mx = fmaxf(mx, v[i]);
    }
    __shared__ float shm[4];
    #pragma unroll
    for (int o = 16; o > 0; o >>= 1) mx = fmaxf(mx, __shfl_xor_sync(0xffffffffu, mx, o));
    if ((t & 31) == 0) shm[t >> 5] = mx;
    __syncthreads();
    mx = fmaxf(fmaxf(shm[0], shm[1]), fmaxf(shm[2], shm[3]));
    float s = 0.f;
    #pragma unroll
    for (int i = 0; i < 4; i++) { v[i] = __expf(v[i] - mx); s += v[i]; }
    #pragma unroll
    for (int o = 16; o > 0; o >>= 1) s += __shfl_xor_sync(0xffffffffu, s, o);
    __shared__ float shs[4];
    if ((t & 31) == 0) shs[t >> 5] = s;
    __syncthreads();
    s = shs[0] + shs[1] + shs[2] + shs[3];
    float inv = 1.f / s;
    #pragma unroll
    for (int i = 0; i < 4; i++) row[t + i * 128] = v[i] * inv;
}

// ---------------- CRF loss (one warp per batch) ----------------
__global__ void crf_loss_kernel(const float* __restrict__ feats, const int* __restrict__ labels,
                                const int* __restrict__ amask, const float* __restrict__ start,
                                const float* __restrict__ endv, const float* __restrict__ trans,
                                float* __restrict__ part)
{
    int w = threadIdx.x >> 5;
    int lane = threadIdx.x & 31;
    int j = (lane < NLAB) ? lane : NLAB - 1;
    const float* em = feats + (long long)w * SEQL * NLAB;
    const int* mk = amask + w * SEQL;
    float tr[NLAB];
    #pragma unroll
    for (int i = 0; i < NLAB; i++) tr[i] = trans[i * NLAB + j];
    float score = start[j] + em[j];
    for (int t = 1; t < SEQL; t++) {
        float c[NLAB];
        float m = -1e30f;
        #pragma unroll
        for (int i = 0; i < NLAB; i++) {
            c[i] = __shfl_sync(0xffffffffu, score, i) + tr[i];
            m = fmaxf(m, c[i]);
        }
        float s = 0.f;
        #pragma unroll
        for (int i = 0; i < NLAB; i++) s += __expf(c[i] - m);
        float nxt = m + __logf(s) + em[t * NLAB + j];
        score = (mk[t] > 0) ? nxt : score;
    }
    float fin = (lane < NLAB) ? score + endv[j] : -1e30f;
    float m = fin;
    #pragma unroll
    for (int o = 16; o > 0; o >>= 1) m = fmaxf(m, __shfl_xor_sync(0xffffffffu, m, o));
    float s = (lane < NLAB) ? __expf(fin - m) : 0.f;
    #pragma unroll
    for (int o = 16; o > 0; o >>= 1) s += __shfl_xor_sync(0xffffffffu, s, o);
    float logZ = m + __logf(s);

    if (lane == 0) {
        const int* tg = labels + w * SEQL;
        float num = start[tg[0]] + em[tg[0]];
        int cnt = (mk[0] > 0) ? 1 : 0;
        for (int t = 1; t < SEQL; t++) {
            float mf = (float)mk[t];
            num += (em[t * NLAB + tg[t]] + trans[tg[t - 1] * NLAB + tg[t]]) * mf;
            cnt += (mk[t] > 0) ? 1 : 0;
        }
        int last = cnt - 1;
        num += endv[tg[last]];
        part[w] = logZ - num;
    }
}

// ---------------- Viterbi (one warp per batch) ----------------
__global__ void viterbi_kernel(const float* __restrict__ feats, const int* __restrict__ amask,
                               const float* __restrict__ start, const float* __restrict__ endv,
                               const float* __restrict__ trans, int* __restrict__ hist,
                               int* __restrict__ tags)
{
    int w = threadIdx.x >> 5;
    int lane = threadIdx.x & 31;
    int j = (lane < NLAB) ? lane : NLAB - 1;
    const float* em = feats + (long long)w * SEQL * NLAB;
    const int* mk = amask + w * SEQL;
    float tr[NLAB];
    #pragma unroll
    for (int i = 0; i < NLAB; i++) tr[i] = trans[i * NLAB + j];
    float score = start[j] + em[j];
    for (int t = 1; t < SEQL; t++) {
        float best = -1e30f;
        int bi = 0;
        #pragma unroll
        for (int i = 0; i < NLAB; i++) {
            float c = __shfl_sync(0xffffffffu, score, i) + tr[i];
            if (c > best) { best = c; bi = i; }
        }
        if (lane < NLAB) hist[((t - 1) * NB + w) * NLAB + j] = bi;
        float nxt = best + em[t * NLAB + j];
        score = (mk[t] > 0) ? nxt : score;
    }
    float fin = score + endv[j];
    int last = 0;
    float bm = -1e30f;
    #pragma unroll
    for (int i = 0; i < NLAB; i++) {
        float c = __shfl_sync(0xffffffffu, fin, i);
        if (c > bm) { bm = c; last = i; }
    }
    if (lane == 0) {
        int tag = last;
        tags[w * SEQL + SEQL - 1] = tag;
        for (int t = SEQL - 2; t >= 0; t--) {
            tag = hist[(t * NB + w) * NLAB + tag];
            tags[w * SEQL + t] = tag;
        }
    }
}

// ---------------- finalize ----------------
__global__ void finalize_kernel(const float* __restrict__ part, const int* __restrict__ tags,
                                float* __restrict__ out, int out_size)
{
    if (threadIdx.x == 0 && out_size > 0) {
        float s = 0.f;
        #pragma unroll
        for (int w = 0; w < NB; w++) s += part[w];
        out[0] = s * (1.f / NB);
    }
    for (int i = threadIdx.x; i < NB * SEQL; i += blockDim.x) {
        if (1 + i < out_size) out[1 + i] = (float)tags[i];
    }
}

// ---------------- host launch ----------------
extern "C" void kernel_launch(void* const* d_in, const int* in_sizes, int n_in,
                              void* d_out, int out_size)
{
    const float* word_emb  = (const float*)d_in[0];
    const float* pos_emb   = (const float*)d_in[1];
    const float* type_emb  = (const float*)d_in[2];
    const float* emb_ln_s  = (const float*)d_in[3];
    const float* emb_ln_b  = (const float*)d_in[4];
    const float* Wq        = (const float*)d_in[5];
    const float* bq        = (const float*)d_in[6];
    const float* Wk        = (const float*)d_in[7];
    const float* bk        = (const float*)d_in[8];
    const float* Wv        = (const float*)d_in[9];
    const float* bv        = (const float*)d_in[10];
    const float* Wo        = (const float*)d_in[11];
    const float* bo        = (const float*)d_in[12];
    const float* ln1_s     = (const float*)d_in[13];
    const float* ln1_b     = (const float*)d_in[14];
    const float* W1        = (const float*)d_in[15];
    const float* b1        = (const float*)d_in[16];
    const float* W2        = (const float*)d_in[17];
    const float* b2        = (const float*)d_in[18];
    const float* ln2_s     = (const float*)d_in[19];
    const float* ln2_b     = (const float*)d_in[20];
    const float* clf_W     = (const float*)d_in[21];
    const float* clf_b     = (const float*)d_in[22];
    const float* crf_start = (const float*)d_in[23];
    const float* crf_end   = (const float*)d_in[24];
    const float* crf_trans = (const float*)d_in[25];
    const int*   input_ids = (const int*)d_in[26];
    const int*   tok_types = (const int*)d_in[27];
    const int*   amask     = (const int*)d_in[28];
    const int*   labels    = (const int*)d_in[29];
    (void)in_sizes; (void)n_in;

    float *X, *T, *Q, *Kb, *V, *Ctx, *H1, *FFb, *Sc, *Feats, *Part;
    int *Hist, *Tags;
    cudaGetSymbolAddress((void**)&X,    gX);
    cudaGetSymbolAddress((void**)&T,    gT);
    cudaGetSymbolAddress((void**)&Q,    gQ);
    cudaGetSymbolAddress((void**)&Kb,   gK);
    cudaGetSymbolAddress((void**)&V,    gV);
    cudaGetSymbolAddress((void**)&Ctx,  gCtx);
    cudaGetSymbolAddress((void**)&H1,   gH1);
    cudaGetSymbolAddress((void**)&FFb,  gFF);
    cudaGetSymbolAddress((void**)&Sc,   gScores);
    cudaGetSymbolAddress((void**)&Feats, gFeats);
    cudaGetSymbolAddress((void**)&Part, gPart);
    cudaGetSymbolAddress((void**)&Hist, gHist);
    cudaGetSymbolAddress((void**)&Tags, gTags);

    // Embedding + LN -> X
    embed_ln_kernel<<<MROWS, 256>>>(input_ids, tok_types, word_emb, pos_emb, type_emb,
                                    emb_ln_s, emb_ln_b, X);

    const long long HH = (long long)HDIM * HDIM;
    const long long SH = (long long)SEQL * HDIM;
    const long long SS = (long long)SEQL * SEQL;

    dim3 gQKV(HDIM / BN, MROWS / BM);            // 12 x 32
    dim3 gScoreGrid(SEQL / BN, SEQL / BM, NB * NHEAD);  // 8 x 4 x 96
    dim3 gCtxGrid(1, SEQL / BM, NB * NHEAD);     // 1 x 4 x 96
    dim3 gFF1(FFDIM / BN, MROWS / BM);           // 48 x 32
    dim3 gClf(1, MROWS / BM);                    // 1 x 32

    for (int l = 0; l < NLAYR; l++) {
        const float* Wq_l = Wq + l * HH;
        const float* Wk_l = Wk + l * HH;
        const float* Wv_l = Wv + l * HH;
        const float* Wo_l = Wo + l * HH;
        const float* W1_l = W1 + (long long)l * HDIM * FFDIM;
        const float* W2_l = W2 + (long long)l * FFDIM * HDIM;

        // Q, K, V projections
        sgemm_kernel<false, 1><<<gQKV, 256>>>(X, HDIM, 0, 0, Wq_l, HDIM, 0, 0,
            Q, HDIM, 0, 0, bq + l * HDIM, nullptr, 0, MROWS, HDIM, HDIM, 1.f, 1);
        sgemm_kernel<false, 1><<<gQKV, 256>>>(X, HDIM, 0, 0, Wk_l, HDIM, 0, 0,
            Kb, HDIM, 0, 0, bk + l * HDIM, nullptr, 0, MROWS, HDIM, HDIM, 1.f, 1);
        sgemm_kernel<false, 1><<<gQKV, 256>>>(X, HDIM, 0, 0, Wv_l, HDIM, 0, 0,
            V, HDIM, 0, 0, bv + l * HDIM, nullptr, 0, MROWS, HDIM, HDIM, 1.f, 1);

        // scores = 0.125 * Q K^T   (batched over b,h)
        sgemm_kernel<true, 0><<<gScoreGrid, 256>>>(Q, HDIM, SH, DHEAD, Kb, HDIM, SH, DHEAD,
            Sc, SEQL, (long long)NHEAD * SS, SS, nullptr, nullptr, 0,
            SEQL, SEQL, DHEAD, 0.125f, NHEAD);

        softmax_kernel<<<dim3(SEQL, NB * NHEAD), 128>>>(Sc, amask);

        // ctx = softmax(scores) @ V   (output directly in (B,S,NH,DH) layout)
        sgemm_kernel<false, 0><<<gCtxGrid, 256>>>(Sc, SEQL, (long long)NHEAD * SS, SS,
            V, HDIM, SH, DHEAD, Ctx, HDIM, SH, DHEAD, nullptr, nullptr, 0,
            SEQL, DHEAD, SEQL, 1.f, NHEAD);

        // attn out + residual, then LN1 -> H1
        sgemm_kernel<false, 2><<<gQKV, 256>>>(Ctx, HDIM, 0, 0, Wo_l, HDIM, 0, 0,
            T, HDIM, 0, 0, bo + l * HDIM, X, HDIM, MROWS, HDIM, HDIM, 1.f, 1);
        layernorm_kernel<<<MROWS, 256>>>(T, H1, ln1_s + l * HDIM, ln1_b + l * HDIM);

        // FF1 + GELU
        sgemm_kernel<false, 3><<<gFF1, 256>>>(H1, HDIM, 0, 0, W1_l, FFDIM, 0, 0,
            FFb, FFDIM, 0, 0, b1 + l * FFDIM, nullptr, 0, MROWS, FFDIM, HDIM, 1.f, 1);

        // FF2 + residual, then LN2 -> X
        sgemm_kernel<false, 2><<<gQKV, 256>>>(FFb, FFDIM, 0, 0, W2_l, HDIM, 0, 0,
            T, HDIM, 0, 0, b2 + l * HDIM, H1, HDIM, MROWS, HDIM, FFDIM, 1.f, 1);
        layernorm_kernel<<<MROWS, 256>>>(T, X, ln2_s + l * HDIM, ln2_b + l * HDIM);
    }

    // classifier
    sgemm_kernel<false, 1><<<gClf, 256>>>(X, HDIM, 0, 0, clf_W, NLAB, 0, 0,
        Feats, NLAB, 0, 0, clf_b, nullptr, 0, MROWS, NLAB, HDIM, 1.f, 1);

    crf_loss_kernel<<<1, 256>>>(Feats, labels, amask, crf_start, crf_end, crf_trans, Part);
    viterbi_kernel<<<1, 256>>>(Feats, amask, crf_start, crf_end, crf_trans, Hist, Tags);
    finalize_kernel<<<1, 512>>>(Part, Tags, (float*)d_out, out_size);
}

// round 8
// speedup vs baseline: 1.3512x; 1.3512x over previous
#include <cuda_runtime.h>
#include <cuda_bf16.h>
#include <math.h>
#include <stdint.h>

// tcgen05 requires the arch-accelerated target (sm_103a / sm_100a / sm_101a).
#if !defined(__CUDA_ARCH__)
#define TC_PATH 1
#elif defined(__CUDA_ARCH_FEAT_SM103_ALL) || defined(__CUDA_ARCH_FEAT_SM100_ALL) || defined(__CUDA_ARCH_FEAT_SM101_ALL)
#define TC_PATH 1
#else
#define TC_PATH 0
#endif

// ---------------- problem constants ----------------
constexpr int HDIM  = 768;
constexpr int SEQL  = 512;
constexpr int NB    = 8;
constexpr int NLAYR = 12;
constexpr int NHEAD = 12;
constexpr int DHEAD = 64;
constexpr int FFDIM = 3072;
constexpr int MROWS = NB * SEQL;   // 4096
constexpr int NLAB  = 9;

// ---------------- device scratch ----------------
__device__ float gX[MROWS * HDIM];
__device__ float gT[MROWS * HDIM];
__device__ float gQ[MROWS * HDIM];
__device__ float gK[MROWS * HDIM];
__device__ float gV[MROWS * HDIM];
__device__ float gCtx[MROWS * HDIM];
__device__ float gH1[MROWS * HDIM];
__device__ float gFF[MROWS * FFDIM];
__device__ float gScores[25165824];          // 8*12*512*512
__device__ float gFeats[MROWS * NLAB];
__device__ float gPart[NB];
__device__ int   gHist[(SEQL - 1) * NB * NLAB];
__device__ int   gTags[NB * SEQL];

// ---------------- smem layout for tc path (bytes) ----------------
constexpr int SM_TMEM = 0;
constexpr int SM_BAR  = 8;
constexpr int SM_AH   = 1024;            // A planes: 128 rows * 128B
constexpr int SM_AM   = SM_AH + 16384;
constexpr int SM_AL   = SM_AM + 16384;
constexpr int SM_BH   = SM_AL + 16384;   // B planes: 64 rows * 128B
constexpr int SM_BM   = SM_BH + 8192;
constexpr int SM_BL   = SM_BM + 8192;
constexpr int SM_TOTAL = SM_BL + 8192;   // 74752

#define SWZ128(b) ((b) ^ (((b) >> 3) & 0x70))

__device__ __forceinline__ void split3u(float x, unsigned short& h,
                                        unsigned short& m, unsigned short& l) {
    __nv_bfloat16 bh = __float2bfloat16(x);
    float r = x - __bfloat162float(bh);
    __nv_bfloat16 bm = __float2bfloat16(r);
    float r2 = r - __bfloat162float(bm);
    __nv_bfloat16 bl = __float2bfloat16(r2);
    h = __bfloat16_as_ushort(bh);
    m = __bfloat16_as_ushort(bm);
    l = __bfloat16_as_ushort(bl);
}

#if TC_PATH
__device__ __forceinline__ uint32_t smem_u32(const void* p) {
    uint32_t a;
    asm("{ .reg .u64 t; cvta.to.shared.u64 t, %1; cvt.u32.u64 %0, t; }" : "=r"(a) : "l"(p));
    return a;
}
__device__ __forceinline__ uint32_t elect_one() {
    uint32_t pred;
    asm volatile("{\n\t.reg .pred p;\n\telect.sync _|p, 0xFFFFFFFF;\n\t"
                 "selp.b32 %0, 1, 0, p;\n\t}" : "=r"(pred));
    return pred;
}
static constexpr uint64_t DESC_BASE_SW128 =
    (uint64_t(2) << 61) | (uint64_t(1) << 46) | (uint64_t(64) << 32) | (uint64_t(1) << 16);
__device__ __forceinline__ uint64_t mk_desc(uint32_t addr) {
    return DESC_BASE_SW128 | ((uint64_t)(addr >> 4) & 0x3FFF);
}
// idesc: dtype F32, a/b BF16, N=64, M=128
constexpr uint32_t TC_IDESC = (1u << 4) | (1u << 7) | (1u << 10) | (8u << 17) | (8u << 24);

__device__ __forceinline__ void mma_f16_ss(uint32_t d, uint64_t a, uint64_t b, uint32_t en) {
    asm volatile(
        "{\n\t.reg .pred p;\n\tsetp.ne.u32 p, %4, 0;\n\t"
        "tcgen05.mma.cta_group::1.kind::f16 [%0], %1, %2, %3, {%5, %5, %5, %5}, p;\n\t}"
        :: "r"(d), "l"(a), "l"(b), "r"(TC_IDESC), "r"(en), "r"(0u) : "memory");
}
__device__ __forceinline__ void tc_commit(uint32_t bar) {
    asm volatile(
        "tcgen05.commit.cta_group::1.mbarrier::arrive::one.shared::cluster.b64 [%0];"
        :: "r"(bar) : "memory");
}
__device__ __forceinline__ void mbar_init(uint32_t bar, uint32_t cnt) {
    asm volatile("mbarrier.init.shared.b64 [%0], %1;" :: "r"(bar), "r"(cnt) : "memory");
}
__device__ __forceinline__ void mbar_inval(uint32_t bar) {
    asm volatile("mbarrier.inval.shared.b64 [%0];" :: "r"(bar) : "memory");
}
__device__ __forceinline__ void mbar_wait(uint32_t bar, uint32_t parity) {
    uint32_t done;
    asm volatile(
        "{\n\t.reg .pred p;\n\t"
        "mbarrier.try_wait.parity.acquire.cta.shared::cta.b64 p, [%1], %2;\n\t"
        "selp.b32 %0, 1, 0, p;\n\t}"
        : "=r"(done) : "r"(bar), "r"(parity) : "memory");
    if (!done) {
        asm volatile(
            "{\n\t.reg .pred P1;\n\t"
            "WL_%=:\n\t"
            "mbarrier.try_wait.parity.acquire.cta.shared::cta.b64 P1, [%0], %1, 0x989680;\n\t"
            "@P1 bra.uni WD_%=;\n\t"
            "bra.uni WL_%=;\n\t"
            "WD_%=:\n\t}"
            :: "r"(bar), "r"(parity) : "memory");
    }
}
#endif // TC_PATH

// =========================================================================
// tc_gemm: C(MxN) = alpha * A(MxK) @ op(B), fp32 in/out.
// tcgen05 path: 3-way bf16 split of both operands, 6 partial MMAs per k16.
// Fallback (plain sm_103): FFMA tile GEMM on the same fp32 inputs.
// BLAYOUT=0: B is [N,K] row-major. BLAYOUT=1: B is [K,N] row-major.
// EPI: 0 none, 1 +bias, 2 +bias+resid, 3 +bias+GELU(exact).
// M%128==0, N%64==0, K%64==0.
// =========================================================================
template<int BLAYOUT, int EPI>
__global__ __launch_bounds__(256)
void tc_gemm(const float* __restrict__ A, int lda, long long sAo, long long sAi,
             const float* __restrict__ B, int ldb, long long sBo, long long sBi,
             float* __restrict__ C, int ldc, long long sCo, long long sCi,
             const float* __restrict__ bias,
             const float* __restrict__ resid, int ldr,
             int M, int N, int K, float alpha, int zdiv)
{
    extern __shared__ __align__(1024) char smem[];
    const int tid = threadIdx.x;

    int z = blockIdx.z;
    int zo = z / zdiv, zi = z - zo * zdiv;
    A += zo * sAo + zi * sAi;
    B += zo * sBo + zi * sBi;
    C += zo * sCo + zi * sCi;

    const int bm = blockIdx.y * 128;
    const int bn = blockIdx.x * 64;

#if TC_PATH
    const uint32_t sbase = smem_u32(smem);
    const int wid = tid >> 5;
    if (wid == 0) {
        asm volatile("tcgen05.alloc.cta_group::1.sync.aligned.shared::cta.b32 [%0], %1;"
                     :: "r"(sbase + SM_TMEM), "r"(64u) : "memory");
    }
    if (tid == 0) mbar_init(sbase + SM_BAR, 1);
    __syncthreads();
    uint32_t tmem;
    asm volatile("ld.shared.b32 %0, [%1];" : "=r"(tmem) : "r"(sbase + SM_TMEM));
    const uint32_t bar = sbase + SM_BAR;

    uint64_t dA[3], dB[3];
    dA[0] = mk_desc(sbase + SM_AH); dA[1] = mk_desc(sbase + SM_AM); dA[2] = mk_desc(sbase + SM_AL);
    dB[0] = mk_desc(sbase + SM_BH); dB[1] = mk_desc(sbase + SM_BM); dB[2] = mk_desc(sbase + SM_BL);

    const int KT = K >> 6;
    const int q  = tid & 15;
    const int r0 = tid >> 4;

    for (int kt = 0; kt < KT; kt++) {
        const int k0 = kt << 6;
        if (kt > 0) mbar_wait(bar, (kt - 1) & 1);

        { // A tile 128x64 -> 3 planes
            const float* Ag = A + (long long)bm * lda + k0;
            #pragma unroll
            for (int p = 0; p < 8; p++) {
                int m = r0 + p * 16;
                float4 v = *(const float4*)(Ag + (long long)m * lda + q * 4);
                unsigned short h[4], md[4], l[4];
                split3u(v.x, h[0], md[0], l[0]);
                split3u(v.y, h[1], md[1], l[1]);
                split3u(v.z, h[2], md[2], l[2]);
                split3u(v.w, h[3], md[3], l[3]);
                int sw = SWZ128(m * 128 + q * 8);
                *(uint2*)(smem + SM_AH + sw) = make_uint2(
                    (uint32_t)h[0] | ((uint32_t)h[1] << 16),
                    (uint32_t)h[2] | ((uint32_t)h[3] << 16));
                *(uint2*)(smem + SM_AM + sw) = make_uint2(
                    (uint32_t)md[0] | ((uint32_t)md[1] << 16),
                    (uint32_t)md[2] | ((uint32_t)md[3] << 16));
                *(uint2*)(smem + SM_AL + sw) = make_uint2(
                    (uint32_t)l[0] | ((uint32_t)l[1] << 16),
                    (uint32_t)l[2] | ((uint32_t)l[3] << 16));
            }
        }
        if (BLAYOUT == 0) { // B [N,K] 64x64 -> planes [n][k]
            const float* Bg = B + (long long)bn * ldb + k0;
            #pragma unroll
            for (int p = 0; p < 4; p++) {
                int n = r0 + p * 16;
                float4 v = *(const float4*)(Bg + (long long)n * ldb + q * 4);
                unsigned short h[4], md[4], l[4];
                split3u(v.x, h[0], md[0], l[0]);
                split3u(v.y, h[1], md[1], l[1]);
                split3u(v.z, h[2], md[2], l[2]);
                split3u(v.w, h[3], md[3], l[3]);
                int sw = SWZ128(n * 128 + q * 8);
                *(uint2*)(smem + SM_BH + sw) = make_uint2(
                    (uint32_t)h[0] | ((uint32_t)h[1] << 16),
                    (uint32_t)h[2] | ((uint32_t)h[3] << 16));
                *(uint2*)(smem + SM_BM + sw) = make_uint2(
                    (uint32_t)md[0] | ((uint32_t)md[1] << 16),
                    (uint32_t)md[2] | ((uint32_t)md[3] << 16));
                *(uint2*)(smem + SM_BL + sw) = make_uint2(
                    (uint32_t)l[0] | ((uint32_t)l[1] << 16),
                    (uint32_t)l[2] | ((uint32_t)l[3] << 16));
            }
        } else {            // B [K,N] -> transpose into planes [n][k]
            const int n4 = (tid & 15) * 4;
            const int kr = tid >> 4;
            const float* Bg = B + (long long)k0 * ldb + bn;
            #pragma unroll
            for (int p = 0; p < 4; p++) {
                int k = kr + p * 16;
                float4 v = *(const float4*)(Bg + (long long)k * ldb + n4);
                float xs[4] = {v.x, v.y, v.z, v.w};
                #pragma unroll
                for (int j = 0; j < 4; j++) {
                    unsigned short h, md, l;
                    split3u(xs[j], h, md, l);
                    int sw = SWZ128((n4 + j) * 128 + k * 2);
                    *(unsigned short*)(smem + SM_BH + sw) = h;
                    *(unsigned short*)(smem + SM_BM + sw) = md;
                    *(unsigned short*)(smem + SM_BL + sw) = l;
                }
            }
        }
        asm volatile("fence.proxy.async.shared::cta;" ::: "memory");
        __syncthreads();

        if (wid == 0) {
            if (elect_one()) {
                #pragma unroll
                for (int s = 0; s < 4; s++) {
                    uint64_t off = 2 * s;
                    uint32_t en0 = (kt != 0 || s != 0) ? 1u : 0u;
                    mma_f16_ss(tmem, dA[0] + off, dB[0] + off, en0);
                    mma_f16_ss(tmem, dA[0] + off, dB[1] + off, 1u);
                    mma_f16_ss(tmem, dA[1] + off, dB[0] + off, 1u);
                    mma_f16_ss(tmem, dA[0] + off, dB[2] + off, 1u);
                    mma_f16_ss(tmem, dA[1] + off, dB[1] + off, 1u);
                    mma_f16_ss(tmem, dA[2] + off, dB[0] + off, 1u);
                }
                tc_commit(bar);
            }
        }
    }

    mbar_wait(bar, (KT - 1) & 1);
    asm volatile("tcgen05.fence::after_thread_sync;" ::: "memory");

    if (tid < 128) {
        uint32_t dr[64];
        asm volatile(
            "tcgen05.ld.sync.aligned.32x32b.x32.b32 "
            "{%0,%1,%2,%3,%4,%5,%6,%7,%8,%9,%10,%11,%12,%13,%14,%15,"
            "%16,%17,%18,%19,%20,%21,%22,%23,%24,%25,%26,%27,%28,%29,%30,%31}, [%32];"
            : "=r"(dr[0]),"=r"(dr[1]),"=r"(dr[2]),"=r"(dr[3]),"=r"(dr[4]),"=r"(dr[5]),
              "=r"(dr[6]),"=r"(dr[7]),"=r"(dr[8]),"=r"(dr[9]),"=r"(dr[10]),"=r"(dr[11]),
              "=r"(dr[12]),"=r"(dr[13]),"=r"(dr[14]),"=r"(dr[15]),"=r"(dr[16]),"=r"(dr[17]),
              "=r"(dr[18]),"=r"(dr[19]),"=r"(dr[20]),"=r"(dr[21]),"=r"(dr[22]),"=r"(dr[23]),
              "=r"(dr[24]),"=r"(dr[25]),"=r"(dr[26]),"=r"(dr[27]),"=r"(dr[28]),"=r"(dr[29]),
              "=r"(dr[30]),"=r"(dr[31])
            : "r"(tmem));
        asm volatile(
            "tcgen05.ld.sync.aligned.32x32b.x32.b32 "
            "{%0,%1,%2,%3,%4,%5,%6,%7,%8,%9,%10,%11,%12,%13,%14,%15,"
            "%16,%17,%18,%19,%20,%21,%22,%23,%24,%25,%26,%27,%28,%29,%30,%31}, [%32];"
            : "=r"(dr[32]),"=r"(dr[33]),"=r"(dr[34]),"=r"(dr[35]),"=r"(dr[36]),"=r"(dr[37]),
              "=r"(dr[38]),"=r"(dr[39]),"=r"(dr[40]),"=r"(dr[41]),"=r"(dr[42]),"=r"(dr[43]),
              "=r"(dr[44]),"=r"(dr[45]),"=r"(dr[46]),"=r"(dr[47]),"=r"(dr[48]),"=r"(dr[49]),
              "=r"(dr[50]),"=r"(dr[51]),"=r"(dr[52]),"=r"(dr[53]),"=r"(dr[54]),"=r"(dr[55]),
              "=r"(dr[56]),"=r"(dr[57]),"=r"(dr[58]),"=r"(dr[59]),"=r"(dr[60]),"=r"(dr[61]),
              "=r"(dr[62]),"=r"(dr[63])
            : "r"(tmem + 32));
        asm volatile("tcgen05.wait::ld.sync.aligned;" ::: "memory");
        asm volatile("tcgen05.fence::before_thread_sync;" ::: "memory");

        int m = bm + (tid >> 5) * 32 + (tid & 31);
        float* Crow = C + (long long)m * ldc + bn;
        const float* Rrow = (EPI == 2) ? (resid + (long long)m * ldr + bn) : nullptr;
        #pragma unroll
        for (int c4 = 0; c4 < 16; c4++) {
            float vv[4];
            #pragma unroll
            for (int j = 0; j < 4; j++) {
                int c = c4 * 4 + j;
                float v = __uint_as_float(dr[c]) * alpha;
                if (EPI >= 1) v += bias[bn + c];
                if (EPI == 2) v += Rrow[c];
                if (EPI == 3) v = 0.5f * v * (1.0f + erff(v * 0.70710678118654752f));
                vv[j] = v;
            }
            float4 o = {vv[0], vv[1], vv[2], vv[3]};
            *(float4*)(Crow + c4 * 4) = o;
        }
    }
    __syncthreads();
    if (tid == 0) mbar_inval(bar);
    if (wid == 0) {
        asm volatile("tcgen05.relinquish_alloc_permit.cta_group::1.sync.aligned;");
        asm volatile("tcgen05.dealloc.cta_group::1.sync.aligned.b32 %0, %1;"
                     :: "r"(tmem), "r"(64u));
    }
#else
    // ---------------- FFMA fallback (plain sm_103 pass) ----------------
    float* As = (float*)smem;          // [16][128]
    float* Bs = As + 16 * 128;         // [16][64]
    const int tx = tid & 15, ty = tid >> 4;
    float acc[8][4];
    #pragma unroll
    for (int i = 0; i < 8; i++)
        #pragma unroll
        for (int j = 0; j < 4; j++) acc[i][j] = 0.f;

    for (int k0 = 0; k0 < K; k0 += 16) {
        {
            int row = tid >> 1, col = (tid & 1) * 8;
            const float* Ag = A + (long long)(bm + row) * lda + k0 + col;
            #pragma unroll
            for (int i = 0; i < 8; i++) As[(col + i) * 128 + row] = Ag[i];
        }
        if (BLAYOUT == 0) {
            int nn = tid >> 2, kk = (tid & 3) * 4;
            const float* Bg = B + (long long)(bn + nn) * ldb + k0 + kk;
            #pragma unroll
            for (int j = 0; j < 4; j++) Bs[(kk + j) * 64 + nn] = Bg[j];
        } else {
            int kk = tid >> 4, nn = (tid & 15) * 4;
            const float* Bg = B + (long long)(k0 + kk) * ldb + bn + nn;
            #pragma unroll
            for (int j = 0; j < 4; j++) Bs[kk * 64 + nn + j] = Bg[j];
        }
        __syncthreads();
        #pragma unroll
        for (int kk = 0; kk < 16; kk++) {
            float a[8], b[4];
            #pragma unroll
            for (int i = 0; i < 8; i++) a[i] = As[kk * 128 + ty * 8 + i];
            #pragma unroll
            for (int j = 0; j < 4; j++) b[j] = Bs[kk * 64 + tx * 4 + j];
            #pragma unroll
            for (int i = 0; i < 8; i++)
                #pragma unroll
                for (int j = 0; j < 4; j++) acc[i][j] = fmaf(a[i], b[j], acc[i][j]);
        }
        __syncthreads();
    }
    #pragma unroll
    for (int i = 0; i < 8; i++) {
        int gm = bm + ty * 8 + i;
        #pragma unroll
        for (int j = 0; j < 4; j++) {
            int gn = bn + tx * 4 + j;
            float v = acc[i][j] * alpha;
            if (EPI >= 1) v += bias[gn];
            if (EPI == 2) v += resid[(long long)gm * ldr + gn];
            if (EPI == 3) v = 0.5f * v * (1.0f + erff(v * 0.70710678118654752f));
            C[(long long)gm * ldc + gn] = v;
        }
    }
#endif
}

// ---------------- block reduce ----------------
__device__ __forceinline__ float blockReduceSum(float v) {
    __shared__ float sh[32];
    int lane = threadIdx.x & 31, wid = threadIdx.x >> 5;
    #pragma unroll
    for (int o = 16; o > 0; o >>= 1) v += __shfl_down_sync(0xffffffffu, v, o);
    if (lane == 0) sh[wid] = v;
    __syncthreads();
    int nw = blockDim.x >> 5;
    v = (threadIdx.x < nw) ? sh[threadIdx.x] : 0.f;
    if (wid == 0) {
        #pragma unroll
        for (int o = 16; o > 0; o >>= 1) v += __shfl_down_sync(0xffffffffu, v, o);
    }
    if (threadIdx.x == 0) sh[0] = v;
    __syncthreads();
    float r = sh[0];
    __syncthreads();
    return r;
}

// ---------------- classifier FFMA GEMM (N=9) ----------------
__global__ __launch_bounds__(256)
void clf_gemm(const float* __restrict__ A, const float* __restrict__ B,
              const float* __restrict__ bias, float* __restrict__ C)
{
    __shared__ float As[16][128];
    __shared__ float Bs[16][NLAB];
    int bm = blockIdx.y * 128;
    int tid = threadIdx.x;
    int tx = tid & 15, ty = tid >> 4;
    float acc[8][4];
    #pragma unroll
    for (int i = 0; i < 8; i++)
        #pragma unroll
        for (int j = 0; j < 4; j++) acc[i][j] = 0.f;
    for (int k0 = 0; k0 < HDIM; k0 += 16) {
        {
            int row = tid >> 1, col = (tid & 1) * 8;
            #pragma unroll
            for (int i = 0; i < 8; i++)
                As[col + i][row] = A[(long long)(bm + row) * HDIM + k0 + col + i];
        }
        if (tid < 16) {
            #pragma unroll
            for (int j = 0; j < NLAB; j++)
                Bs[tid][j] = B[(long long)(k0 + tid) * NLAB + j];
        }
        __syncthreads();
        #pragma unroll
        for (int kk = 0; kk < 16; kk++) {
            float a[8];
            #pragma unroll
            for (int i = 0; i < 8; i++) a[i] = As[kk][ty * 8 + i];
            #pragma unroll
            for (int j = 0; j < 4; j++) {
                int gn = tx * 4 + j;
                float bv = (gn < NLAB) ? Bs[kk][gn] : 0.f;
                #pragma unroll
                for (int i = 0; i < 8; i++) acc[i][j] = fmaf(a[i], bv, acc[i][j]);
            }
        }
        __syncthreads();
    }
    #pragma unroll
    for (int i = 0; i < 8; i++) {
        int gm = bm + ty * 8 + i;
        #pragma unroll
        for (int j = 0; j < 4; j++) {
            int gn = tx * 4 + j;
            if (gn < NLAB) C[(long long)gm * NLAB + gn] = acc[i][j] + bias[gn];
        }
    }
}

__global__ void embed_ln_kernel(const int* __restrict__ ids, const int* __restrict__ tts,
                                const float* __restrict__ we, const float* __restrict__ pe,
                                const float* __restrict__ te, const float* __restrict__ s,
                                const float* __restrict__ b, float* __restrict__ out)
{
    int n = blockIdx.x;
    int sp = n & (SEQL - 1);
    int id = ids[n];
    int tt = tts[n];
    float v[3];
    float sum = 0.f;
    #pragma unroll
    for (int i = 0; i < 3; i++) {
        int h = threadIdx.x + i * 256;
        v[i] = we[(long long)id * HDIM + h] + pe[sp * HDIM + h] + te[tt * HDIM + h];
        sum += v[i];
    }
    float mean = blockReduceSum(sum) * (1.f / HDIM);
    float vs = 0.f;
    #pragma unroll
    for (int i = 0; i < 3; i++) { float d = v[i] - mean; vs += d * d; }
    float var = blockReduceSum(vs) * (1.f / HDIM);
    float inv = rsqrtf(var + 1e-12f);
    #pragma unroll
    for (int i = 0; i < 3; i++) {
        int h = threadIdx.x + i * 256;
        out[(long long)n * HDIM + h] = (v[i] - mean) * inv * s[h] + b[h];
    }
}

__global__ void layernorm_kernel(const float* __restrict__ in, float* __restrict__ out,
                                 const float* __restrict__ s, const float* __restrict__ b)
{
    int n = blockIdx.x;
    const float* row = in + (long long)n * HDIM;
    float v[3];
    float sum = 0.f;
    #pragma unroll
    for (int i = 0; i < 3; i++) { v[i] = row[threadIdx.x + i * 256]; sum += v[i]; }
    float mean = blockReduceSum(sum) * (1.f / HDIM);
    float vs = 0.f;
    #pragma unroll
    for (int i = 0; i < 3; i++) { float d = v[i] - mean; vs += d * d; }
    float var = blockReduceSum(vs) * (1.f / HDIM);
    float inv = rsqrtf(var + 1e-12f);
    #pragma unroll
    for (int i = 0; i < 3; i++) {
        int h = threadIdx.x + i * 256;
        out[(long long)n * HDIM + h] = (v[i] - mean) * inv * s[h] + b[h];
    }
}

__global__ void softmax_kernel(float* __restrict__ sc, const int* __restrict__ amask)
{
    int q = blockIdx.x;
    int bh = blockIdx.y;
    int b = bh / NHEAD;
    float* row = sc + ((long long)bh * SEQL + q) * SEQL;
    const int* mrow = amask + b * SEQL;
    int t = threadIdx.x;
    float v[4];
    float mx = -1e30f;
    #pragma unroll
    for (int i = 0; i < 4; i++) {
        int k = t + i * 128;
        float bias = (mrow[k] > 0) ? 0.f : -10000.f;
        v[i] = row[k] + bias;
        mx = fmaxf(mx, v[i]);
    }
    __shared__ float shm[4];
    #pragma unroll
    for (int o = 16; o > 0; o >>= 1) mx = fmaxf(mx, __shfl_xor_sync(0xffffffffu, mx, o));
    if ((t & 31) == 0) shm[t >> 5] = mx;
    __syncthreads();
    mx = fmaxf(fmaxf(shm[0], shm[1]), fmaxf(shm[2], shm[3]));
    float s = 0.f;
    #pragma unroll
    for (int i = 0; i < 4; i++) { v[i] = __expf(v[i] - mx); s += v[i]; }
    #pragma unroll
    for (int o = 16; o > 0; o >>= 1) s += __shfl_xor_sync(0xffffffffu, s, o);
    __shared__ float shs[4];
    if ((t & 31) == 0) shs[t >> 5] = s;
    __syncthreads();
    s = shs[0] + shs[1] + shs[2] + shs[3];
    float inv = 1.f / s;
    #pragma unroll
    for (int i = 0; i < 4; i++) row[t + i * 128] = v[i] * inv;
}

__global__ void crf_loss_kernel(const float* __restrict__ feats, const int* __restrict__ labels,
                                const int* __restrict__ amask, const float* __restrict__ start,
                                const float* __restrict__ endv, const float* __restrict__ trans,
                                float* __restrict__ part)
{
    int w = threadIdx.x >> 5;
    int lane = threadIdx.x & 31;
    int j = (lane < NLAB) ? lane : NLAB - 1;
    const float* em = feats + (long long)w * SEQL * NLAB;
    const int* mk = amask + w * SEQL;
    float tr[NLAB];
    #pragma unroll
    for (int i = 0; i < NLAB; i++) tr[i] = trans[i * NLAB + j];
    float score = start[j] + em[j];
    for (int t = 1; t < SEQL; t++) {
        float c[NLAB];
        float m = -1e30f;
        #pragma unroll
        for (int i = 0; i < NLAB; i++) {
            c[i] = __shfl_sync(0xffffffffu, score, i) + tr[i];
            m = fmaxf(m, c[i]);
        }
        float s = 0.f;
        #pragma unroll
        for (int i = 0; i < NLAB; i++) s += __expf(c[i] - m);
        float nxt = m + __logf(s) + em[t * NLAB + j];
        score = (mk[t] > 0) ? nxt : score;
    }
    float fin = (lane < NLAB) ? score + endv[j] : -1e30f;
    float m = fin;
    #pragma unroll
    for (int o = 16; o > 0; o >>= 1) m = fmaxf(m, __shfl_xor_sync(0xffffffffu, m, o));
    float s = (lane < NLAB) ? __expf(fin - m) : 0.f;
    #pragma unroll
    for (int o = 16; o > 0; o >>= 1) s += __shfl_xor_sync(0xffffffffu, s, o);
    float logZ = m + __logf(s);
    if (lane == 0) {
        const int* tg = labels + w * SEQL;
        float num = start[tg[0]] + em[tg[0]];
        int cnt = (mk[0] > 0) ? 1 : 0;
        for (int t = 1; t < SEQL; t++) {
            float mf = (float)mk[t];
            num += (em[t * NLAB + tg[t]] + trans[tg[t - 1] * NLAB + tg[t]]) * mf;
            cnt += (mk[t] > 0) ? 1 : 0;
        }
        int last = cnt - 1;
        num += endv[tg[last]];
        part[w] = logZ - num;
    }
}

__global__ void viterbi_kernel(const float* __restrict__ feats, const int* __restrict__ amask,
                               const float* __restrict__ start, const float* __restrict__ endv,
                               const float* __restrict__ trans, int* __restrict__ hist,
                               int* __restrict__ tags)
{
    int w = threadIdx.x >> 5;
    int lane = threadIdx.x & 31;
    int j = (lane < NLAB) ? lane : NLAB - 1;
    const float* em = feats + (long long)w * SEQL * NLAB;
    const int* mk = amask + w * SEQL;
    float tr[NLAB];
    #pragma unroll
    for (int i = 0; i < NLAB; i++) tr[i] = trans[i * NLAB + j];
    float score = start[j] + em[j];
    for (int t = 1; t < SEQL; t++) {
        float best = -1e30f;
        int bi = 0;
        #pragma unroll
        for (int i = 0; i < NLAB; i++) {
            float c = __shfl_sync(0xffffffffu, score, i) + tr[i];
            if (c > best) { best = c; bi = i; }
        }
        if (lane < NLAB) hist[((t - 1) * NB + w) * NLAB + j] = bi;
        float nxt = best + em[t * NLAB + j];
        score = (mk[t] > 0) ? nxt : score;
    }
    float fin = score + endv[j];
    int last = 0;
    float bm = -1e30f;
    #pragma unroll
    for (int i = 0; i < NLAB; i++) {
        float c = __shfl_sync(0xffffffffu, fin, i);
        if (c > bm) { bm = c; last = i; }
    }
    if (lane == 0) {
        int tag = last;
        tags[w * SEQL + SEQL - 1] = tag;
        for (int t = SEQL - 2; t >= 0; t--) {
            tag = hist[(t * NB + w) * NLAB + tag];
            tags[w * SEQL + t] = tag;
        }
    }
}

__global__ void finalize_kernel(const float* __restrict__ part, const int* __restrict__ tags,
                                float* __restrict__ out, int out_size)
{
    if (threadIdx.x == 0 && out_size > 0) {
        float s = 0.f;
        #pragma unroll
        for (int w = 0; w < NB; w++) s += part[w];
        out[0] = s * (1.f / NB);
    }
    for (int i = threadIdx.x; i < NB * SEQL; i += blockDim.x) {
        if (1 + i < out_size) out[1 + i] = (float)tags[i];
    }
}

// ---------------- host launch ----------------
extern "C" void kernel_launch(void* const* d_in, const int* in_sizes, int n_in,
                              void* d_out, int out_size)
{
    const float* word_emb  = (const float*)d_in[0];
    const float* pos_emb   = (const float*)d_in[1];
    const float* type_emb  = (const float*)d_in[2];
    const float* emb_ln_s  = (const float*)d_in[3];
    const float* emb_ln_b  = (const float*)d_in[4];
    const float* Wq        = (const float*)d_in[5];
    const float* bq        = (const float*)d_in[6];
    const float* Wk        = (const float*)d_in[7];
    const float* bk        = (const float*)d_in[8];
    const float* Wv        = (const float*)d_in[9];
    const float* bv        = (const float*)d_in[10];
    const float* Wo        = (const float*)d_in[11];
    const float* bo        = (const float*)d_in[12];
    const float* ln1_s     = (const float*)d_in[13];
    const float* ln1_b     = (const float*)d_in[14];
    const float* W1        = (const float*)d_in[15];
    const float* b1        = (const float*)d_in[16];
    const float* W2        = (const float*)d_in[17];
    const float* b2        = (const float*)d_in[18];
    const float* ln2_s     = (const float*)d_in[19];
    const float* ln2_b     = (const float*)d_in[20];
    const float* clf_W     = (const float*)d_in[21];
    const float* clf_b     = (const float*)d_in[22];
    const float* crf_start = (const float*)d_in[23];
    const float* crf_end   = (const float*)d_in[24];
    const float* crf_trans = (const float*)d_in[25];
    const int*   input_ids = (const int*)d_in[26];
    const int*   tok_types = (const int*)d_in[27];
    const int*   amask     = (const int*)d_in[28];
    const int*   labels    = (const int*)d_in[29];
    (void)in_sizes; (void)n_in;

    float *X, *T, *Q, *Kb, *V, *Ctx, *H1, *FFb, *Sc, *Feats, *Part;
    int *Hist, *Tags;
    cudaGetSymbolAddress((void**)&X,    gX);
    cudaGetSymbolAddress((void**)&T,    gT);
    cudaGetSymbolAddress((void**)&Q,    gQ);
    cudaGetSymbolAddress((void**)&Kb,   gK);
    cudaGetSymbolAddress((void**)&V,    gV);
    cudaGetSymbolAddress((void**)&Ctx,  gCtx);
    cudaGetSymbolAddress((void**)&H1,   gH1);
    cudaGetSymbolAddress((void**)&FFb,  gFF);
    cudaGetSymbolAddress((void**)&Sc,   gScores);
    cudaGetSymbolAddress((void**)&Feats, gFeats);
    cudaGetSymbolAddress((void**)&Part, gPart);
    cudaGetSymbolAddress((void**)&Hist, gHist);
    cudaGetSymbolAddress((void**)&Tags, gTags);

    cudaFuncSetAttribute(tc_gemm<1,1>, cudaFuncAttributeMaxDynamicSharedMemorySize, SM_TOTAL);
    cudaFuncSetAttribute(tc_gemm<0,0>, cudaFuncAttributeMaxDynamicSharedMemorySize, SM_TOTAL);
    cudaFuncSetAttribute(tc_gemm<1,0>, cudaFuncAttributeMaxDynamicSharedMemorySize, SM_TOTAL);
    cudaFuncSetAttribute(tc_gemm<1,2>, cudaFuncAttributeMaxDynamicSharedMemorySize, SM_TOTAL);
    cudaFuncSetAttribute(tc_gemm<1,3>, cudaFuncAttributeMaxDynamicSharedMemorySize, SM_TOTAL);

    embed_ln_kernel<<<MROWS, 256>>>(input_ids, tok_types, word_emb, pos_emb, type_emb,
                                    emb_ln_s, emb_ln_b, X);

    const long long HH = (long long)HDIM * HDIM;
    const long long SH = (long long)SEQL * HDIM;
    const long long SS = (long long)SEQL * SEQL;

    dim3 gQKV(HDIM / 64, MROWS / 128);                 // 12 x 32
    dim3 gScoreGrid(SEQL / 64, SEQL / 128, NB * NHEAD);// 8 x 4 x 96
    dim3 gCtxGrid(1, SEQL / 128, NB * NHEAD);          // 1 x 4 x 96
    dim3 gFF1(FFDIM / 64, MROWS / 128);                // 48 x 32
    dim3 gClf(1, MROWS / 128);

    for (int l = 0; l < NLAYR; l++) {
        const float* Wq_l = Wq + l * HH;
        const float* Wk_l = Wk + l * HH;
        const float* Wv_l = Wv + l * HH;
        const float* Wo_l = Wo + l * HH;
        const float* W1_l = W1 + (long long)l * HDIM * FFDIM;
        const float* W2_l = W2 + (long long)l * FFDIM * HDIM;

        tc_gemm<1,1><<<gQKV, 256, SM_TOTAL>>>(X, HDIM, 0, 0, Wq_l, HDIM, 0, 0,
            Q, HDIM, 0, 0, bq + l * HDIM, nullptr, 0, MROWS, HDIM, HDIM, 1.f, 1);
        tc_gemm<1,1><<<gQKV, 256, SM_TOTAL>>>(X, HDIM, 0, 0, Wk_l, HDIM, 0, 0,
            Kb, HDIM, 0, 0, bk + l * HDIM, nullptr, 0, MROWS, HDIM, HDIM, 1.f, 1);
        tc_gemm<1,1><<<gQKV, 256, SM_TOTAL>>>(X, HDIM, 0, 0, Wv_l, HDIM, 0, 0,
            V, HDIM, 0, 0, bv + l * HDIM, nullptr, 0, MROWS, HDIM, HDIM, 1.f, 1);

        tc_gemm<0,0><<<gScoreGrid, 256, SM_TOTAL>>>(Q, HDIM, SH, DHEAD, Kb, HDIM, SH, DHEAD,
            Sc, SEQL, (long long)NHEAD * SS, SS, nullptr, nullptr, 0,
            SEQL, SEQL, DHEAD, 0.125f, NHEAD);

        softmax_kernel<<<dim3(SEQL, NB * NHEAD), 128>>>(Sc, amask);

        tc_gemm<1,0><<<gCtxGrid, 256, SM_TOTAL>>>(Sc, SEQL, (long long)NHEAD * SS, SS,
            V, HDIM, SH, DHEAD, Ctx, HDIM, SH, DHEAD, nullptr, nullptr, 0,
            SEQL, DHEAD, SEQL, 1.f, NHEAD);

        tc_gemm<1,2><<<gQKV, 256, SM_TOTAL>>>(Ctx, HDIM, 0, 0, Wo_l, HDIM, 0, 0,
            T, HDIM, 0, 0, bo + l * HDIM, X, HDIM, MROWS, HDIM, HDIM, 1.f, 1);
        layernorm_kernel<<<MROWS, 256>>>(T, H1, ln1_s + l * HDIM, ln1_b + l * HDIM);

        tc_gemm<1,3><<<gFF1, 256, SM_TOTAL>>>(H1, HDIM, 0, 0, W1_l, FFDIM, 0, 0,
            FFb, FFDIM, 0, 0, b1 + l * FFDIM, nullptr, 0, MROWS, FFDIM, HDIM, 1.f, 1);

        tc_gemm<1,2><<<gQKV, 256, SM_TOTAL>>>(FFb, FFDIM, 0, 0, W2_l, HDIM, 0, 0,
            T, HDIM, 0, 0, b2 + l * HDIM, H1, HDIM, MROWS, HDIM, FFDIM, 1.f, 1);
        layernorm_kernel<<<MROWS, 256>>>(T, X, ln2_s + l * HDIM, ln2_b + l * HDIM);
    }

    clf_gemm<<<gClf, 256>>>(X, clf_W, clf_b, Feats);

    crf_loss_kernel<<<1, 256>>>(Feats, labels, amask, crf_start, crf_end, crf_trans, Part);
    viterbi_kernel<<<1, 256>>>(Feats, amask, crf_start, crf_end, crf_trans, Hist, Tags);
    finalize_kernel<<<1, 512>>>(Part, Tags, (float*)d_out, out_size);
}

// round 13
// speedup vs baseline: 1.9795x; 1.4649x over previous
#include <cuda_runtime.h>
#include <cuda_bf16.h>
#include <math.h>
#include <stdint.h>

#if !defined(__CUDA_ARCH__)
#define TC_PATH 1
#elif defined(__CUDA_ARCH_FEAT_SM103_ALL) || defined(__CUDA_ARCH_FEAT_SM100_ALL) || defined(__CUDA_ARCH_FEAT_SM101_ALL)
#define TC_PATH 1
#else
#define TC_PATH 0
#endif

typedef __nv_bfloat16 bf16;

constexpr int HDIM  = 768;
constexpr int SEQL  = 512;
constexpr int NB    = 8;
constexpr int NLAYR = 12;
constexpr int NHEAD = 12;
constexpr int DHEAD = 64;
constexpr int FFDIM = 3072;
constexpr int MROWS = NB * SEQL;
constexpr int NLAB  = 9;
constexpr int NBH   = NB * NHEAD;                 // 96
constexpr long long SH  = (long long)SEQL * HDIM;
constexpr long long SS  = (long long)SEQL * SEQL;
constexpr long long NXH = (long long)MROWS * HDIM;      // 3145728
constexpr long long NFF = (long long)MROWS * FFDIM;     // 12582912
constexpr long long NPP = 25165824LL;                   // scores elems
constexpr long long NVT = (long long)NBH * DHEAD * SEQL;// 3145728
constexpr long long NHH = (long long)HDIM * HDIM;
constexpr long long NHF = (long long)HDIM * FFDIM;

// ---------------- fp32 scratch ----------------
__device__ float gX [NXH];
__device__ float gT [NXH];
__device__ float gQ [NXH];
__device__ float gK [NXH];
__device__ float gV [NXH];
__device__ float gCtx[NXH];
__device__ float gH1[NXH];
__device__ float gFF[NFF];
__device__ float gSc[NPP];
__device__ float gFeats[MROWS * NLAB];
__device__ float gPart[NB];
__device__ int   gHist[(SEQL - 1) * NB * NLAB];
__device__ int   gTags[NB * SEQL];

// ---------------- bf16x3 planes ----------------
__device__ __align__(256) bf16 aX [3 * NXH];
__device__ __align__(256) bf16 aQ [3 * NXH];
__device__ __align__(256) bf16 aK [3 * NXH];
__device__ __align__(256) bf16 aCtx[3 * NXH];
__device__ __align__(256) bf16 aH1[3 * NXH];
__device__ __align__(256) bf16 aFF[3 * NFF];
__device__ __align__(256) bf16 aP [3 * NPP];
__device__ __align__(256) bf16 aVt[3 * NVT];
__device__ __align__(256) bf16 wQt[3 * NHH];
__device__ __align__(256) bf16 wKt[3 * NHH];
__device__ __align__(256) bf16 wVt[3 * NHH];
__device__ __align__(256) bf16 wOt[3 * NHH];
__device__ __align__(256) bf16 w1t[3 * NHF];
__device__ __align__(256) bf16 w2t[3 * NHF];

// ---------------- helpers ----------------
__device__ __forceinline__ void split3(float x, bf16& h, bf16& m, bf16& l) {
    h = __float2bfloat16(x);
    float r = x - __bfloat162float(h);
    m = __float2bfloat16(r);
    l = __float2bfloat16(r - __bfloat162float(m));
}
__device__ __forceinline__ uint32_t pk2(bf16 a, bf16 b) {
    return (uint32_t)__bfloat16_as_ushort(a) | ((uint32_t)__bfloat16_as_ushort(b) << 16);
}
__device__ __forceinline__ float rec3(const bf16* h, const bf16* m, const bf16* l,
                                      long long i) {
    return __bfloat162float(h[i]) + __bfloat162float(m[i]) + __bfloat162float(l[i]);
}
__device__ __forceinline__ float blockReduceSum(float v) {
    __shared__ float sh[32];
    int lane = threadIdx.x & 31, wid = threadIdx.x >> 5;
    #pragma unroll
    for (int o = 16; o > 0; o >>= 1) v += __shfl_down_sync(0xffffffffu, v, o);
    if (lane == 0) sh[wid] = v;
    __syncthreads();
    int nw = blockDim.x >> 5;
    v = (threadIdx.x < nw) ? sh[threadIdx.x] : 0.f;
    if (wid == 0) {
        #pragma unroll
        for (int o = 16; o > 0; o >>= 1) v += __shfl_down_sync(0xffffffffu, v, o);
    }
    if (threadIdx.x == 0) sh[0] = v;
    __syncthreads();
    float r = sh[0];
    __syncthreads();
    return r;
}

// smem layout for tc_gemm3
constexpr int SM_TMEM = 0;
constexpr int SM_BAR  = 8;
constexpr int SM_AH   = 1024;
constexpr int SM_AM   = SM_AH + 16384;
constexpr int SM_AL   = SM_AM + 16384;
constexpr int SM_BH   = SM_AL + 16384;
constexpr int SM_BM   = SM_BH + 8192;
constexpr int SM_BL   = SM_BM + 8192;
constexpr int SM_TOTAL = SM_BL + 8192;   // 74752
#define SWZ128(b) ((b) ^ (((b) >> 3) & 0x70))

#if TC_PATH
__device__ __forceinline__ uint32_t smem_u32(const void* p) {
    uint32_t a;
    asm("{ .reg .u64 t; cvta.to.shared.u64 t, %1; cvt.u32.u64 %0, t; }" : "=r"(a) : "l"(p));
    return a;
}
__device__ __forceinline__ uint32_t elect_one() {
    uint32_t pred;
    asm volatile("{\n\t.reg .pred p;\n\telect.sync _|p, 0xFFFFFFFF;\n\t"
                 "selp.b32 %0, 1, 0, p;\n\t}" : "=r"(pred));
    return pred;
}
static constexpr uint64_t DESC_BASE_SW128 =
    (uint64_t(2) << 61) | (uint64_t(1) << 46) | (uint64_t(64) << 32) | (uint64_t(1) << 16);
__device__ __forceinline__ uint64_t mk_desc(uint32_t addr) {
    return DESC_BASE_SW128 | ((uint64_t)(addr >> 4) & 0x3FFF);
}
constexpr uint32_t TC_IDESC = (1u << 4) | (1u << 7) | (1u << 10) | (8u << 17) | (8u << 24);

__device__ __forceinline__ void mma_f16_ss(uint32_t d, uint64_t a, uint64_t b, uint32_t en) {
    asm volatile(
        "{\n\t.reg .pred p;\n\tsetp.ne.u32 p, %4, 0;\n\t"
        "tcgen05.mma.cta_group::1.kind::f16 [%0], %1, %2, %3, {%5, %5, %5, %5}, p;\n\t}"
        :: "r"(d), "l"(a), "l"(b), "r"(TC_IDESC), "r"(en), "r"(0u) : "memory");
}
__device__ __forceinline__ void tc_commit(uint32_t bar) {
    asm volatile(
        "tcgen05.commit.cta_group::1.mbarrier::arrive::one.shared::cluster.b64 [%0];"
        :: "r"(bar) : "memory");
}
__device__ __forceinline__ void mbar_init(uint32_t bar, uint32_t cnt) {
    asm volatile("mbarrier.init.shared.b64 [%0], %1;" :: "r"(bar), "r"(cnt) : "memory");
}
__device__ __forceinline__ void mbar_inval(uint32_t bar) {
    asm volatile("mbarrier.inval.shared.b64 [%0];" :: "r"(bar) : "memory");
}
__device__ __forceinline__ void mbar_wait(uint32_t bar, uint32_t parity) {
    uint32_t done;
    asm volatile(
        "{\n\t.reg .pred p;\n\t"
        "mbarrier.try_wait.parity.acquire.cta.shared::cta.b64 p, [%1], %2;\n\t"
        "selp.b32 %0, 1, 0, p;\n\t}"
        : "=r"(done) : "r"(bar), "r"(parity) : "memory");
    if (!done) {
        asm volatile(
            "{\n\t.reg .pred P1;\n\t"
            "WL_%=:\n\t"
            "mbarrier.try_wait.parity.acquire.cta.shared::cta.b64 P1, [%0], %1, 0x989680;\n\t"
            "@P1 bra.uni WD_%=;\n\t"
            "bra.uni WL_%=;\n\t"
            "WD_%=:\n\t}"
            :: "r"(bar), "r"(parity) : "memory");
    }
}
#endif

// =========================================================================
// tc_gemm3: C = alpha*A@B^T + epi.  A,B given as bf16x3 planes, both
// K-major: A rows [m][k] (lda), B rows [n][k] (ldb). fp32 C out.
// EPI: 0 none, 1 +bias, 2 +bias+resid, 3 +bias+GELU.  M%128,N%64,K%64==0.
// =========================================================================
template<int EPI>
__global__ __launch_bounds__(256)
void tc_gemm3(const bf16* __restrict__ Ah, const bf16* __restrict__ Am,
              const bf16* __restrict__ Al, int lda, long long sAo, long long sAi,
              const bf16* __restrict__ Bh, const bf16* __restrict__ Bm,
              const bf16* __restrict__ Bl, int ldb, long long sBo, long long sBi,
              float* __restrict__ C, int ldc, long long sCo, long long sCi,
              const float* __restrict__ bias, const float* __restrict__ resid, int ldr,
              int M, int N, int K, float alpha, int zdiv)
{
    extern __shared__ __align__(1024) char smem[];
    const int tid = threadIdx.x;
    int z = blockIdx.z;
    int zo = z / zdiv, zi = z - zo * zdiv;
    long long ao = zo * sAo + zi * sAi;
    long long bo = zo * sBo + zi * sBi;
    Ah += ao; Am += ao; Al += ao;
    Bh += bo; Bm += bo; Bl += bo;
    C  += zo * sCo + zi * sCi;
    const int bm = blockIdx.y * 128;
    const int bn = blockIdx.x * 64;

#if TC_PATH
    const uint32_t sbase = smem_u32(smem);
    const int wid = tid >> 5;
    if (wid == 0) {
        asm volatile("tcgen05.alloc.cta_group::1.sync.aligned.shared::cta.b32 [%0], %1;"
                     :: "r"(sbase + SM_TMEM), "r"(64u) : "memory");
        // release the alloc permit NOW so a second CTA on this SM can allocate
        asm volatile("tcgen05.relinquish_alloc_permit.cta_group::1.sync.aligned;");
    }
    if (tid == 0) mbar_init(sbase + SM_BAR, 1);
    __syncthreads();
    uint32_t tmem;
    asm volatile("ld.shared.b32 %0, [%1];" : "=r"(tmem) : "r"(sbase + SM_TMEM));
    const uint32_t bar = sbase + SM_BAR;

    uint64_t dA[3], dB[3];
    dA[0] = mk_desc(sbase + SM_AH); dA[1] = mk_desc(sbase + SM_AM); dA[2] = mk_desc(sbase + SM_AL);
    dB[0] = mk_desc(sbase + SM_BH); dB[1] = mk_desc(sbase + SM_BM); dB[2] = mk_desc(sbase + SM_BL);

    const int KT = K >> 6;
    const int ar = tid >> 1, ah = tid & 1;   // A: row 0..127, 64B half
    const int br = tid >> 2, bs = tid & 3;   // B: row 0..63, 32B seg

    for (int kt = 0; kt < KT; kt++) {
        const int k0 = kt << 6;
        if (kt > 0) mbar_wait(bar, (kt - 1) & 1);

        { // A planes: 128x64 bf16 each, pure copy with swizzle
            long long g = (long long)(bm + ar) * lda + k0 + ah * 32;
            int so = ar * 128 + ah * 64;
            #pragma unroll
            for (int i = 0; i < 4; i++) {
                int sw = SWZ128(so + i * 16);
                *(uint4*)(smem + SM_AH + sw) = *(const uint4*)(Ah + g + i * 8);
                *(uint4*)(smem + SM_AM + sw) = *(const uint4*)(Am + g + i * 8);
                *(uint4*)(smem + SM_AL + sw) = *(const uint4*)(Al + g + i * 8);
            }
        }
        { // B planes: 64x64 bf16 each
            long long g = (long long)(bn + br) * ldb + k0 + bs * 16;
            int so = br * 128 + bs * 32;
            #pragma unroll
            for (int i = 0; i < 2; i++) {
                int sw = SWZ128(so + i * 16);
                *(uint4*)(smem + SM_BH + sw) = *(const uint4*)(Bh + g + i * 8);
                *(uint4*)(smem + SM_BM + sw) = *(const uint4*)(Bm + g + i * 8);
                *(uint4*)(smem + SM_BL + sw) = *(const uint4*)(Bl + g + i * 8);
            }
        }
        asm volatile("fence.proxy.async.shared::cta;" ::: "memory");
        __syncthreads();

        if (wid == 0) {
            if (elect_one()) {
                #pragma unroll
                for (int s = 0; s < 4; s++) {
                    uint64_t off = 2 * s;
                    uint32_t en0 = (kt != 0 || s != 0) ? 1u : 0u;
                    mma_f16_ss(tmem, dA[0] + off, dB[0] + off, en0); // hh
                    mma_f16_ss(tmem, dA[0] + off, dB[1] + off, 1u);  // hm
                    mma_f16_ss(tmem, dA[1] + off, dB[0] + off, 1u);  // mh
                    mma_f16_ss(tmem, dA[0] + off, dB[2] + off, 1u);  // hl
                    mma_f16_ss(tmem, dA[1] + off, dB[1] + off, 1u);  // mm
                    mma_f16_ss(tmem, dA[2] + off, dB[0] + off, 1u);  // lh
                }
                tc_commit(bar);
            }
        }
    }

    mbar_wait(bar, (KT - 1) & 1);
    asm volatile("tcgen05.fence::after_thread_sync;" ::: "memory");

    if (tid < 128) {
        uint32_t dr[64];
        asm volatile(
            "tcgen05.ld.sync.aligned.32x32b.x32.b32 "
            "{%0,%1,%2,%3,%4,%5,%6,%7,%8,%9,%10,%11,%12,%13,%14,%15,"
            "%16,%17,%18,%19,%20,%21,%22,%23,%24,%25,%26,%27,%28,%29,%30,%31}, [%32];"
            : "=r"(dr[0]),"=r"(dr[1]),"=r"(dr[2]),"=r"(dr[3]),"=r"(dr[4]),"=r"(dr[5]),
              "=r"(dr[6]),"=r"(dr[7]),"=r"(dr[8]),"=r"(dr[9]),"=r"(dr[10]),"=r"(dr[11]),
              "=r"(dr[12]),"=r"(dr[13]),"=r"(dr[14]),"=r"(dr[15]),"=r"(dr[16]),"=r"(dr[17]),
              "=r"(dr[18]),"=r"(dr[19]),"=r"(dr[20]),"=r"(dr[21]),"=r"(dr[22]),"=r"(dr[23]),
              "=r"(dr[24]),"=r"(dr[25]),"=r"(dr[26]),"=r"(dr[27]),"=r"(dr[28]),"=r"(dr[29]),
              "=r"(dr[30]),"=r"(dr[31])
            : "r"(tmem));
        asm volatile(
            "tcgen05.ld.sync.aligned.32x32b.x32.b32 "
            "{%0,%1,%2,%3,%4,%5,%6,%7,%8,%9,%10,%11,%12,%13,%14,%15,"
            "%16,%17,%18,%19,%20,%21,%22,%23,%24,%25,%26,%27,%28,%29,%30,%31}, [%32];"
            : "=r"(dr[32]),"=r"(dr[33]),"=r"(dr[34]),"=r"(dr[35]),"=r"(dr[36]),"=r"(dr[37]),
              "=r"(dr[38]),"=r"(dr[39]),"=r"(dr[40]),"=r"(dr[41]),"=r"(dr[42]),"=r"(dr[43]),
              "=r"(dr[44]),"=r"(dr[45]),"=r"(dr[46]),"=r"(dr[47]),"=r"(dr[48]),"=r"(dr[49]),
              "=r"(dr[50]),"=r"(dr[51]),"=r"(dr[52]),"=r"(dr[53]),"=r"(dr[54]),"=r"(dr[55]),
              "=r"(dr[56]),"=r"(dr[57]),"=r"(dr[58]),"=r"(dr[59]),"=r"(dr[60]),"=r"(dr[61]),
              "=r"(dr[62]),"=r"(dr[63])
            : "r"(tmem + 32));
        asm volatile("tcgen05.wait::ld.sync.aligned;" ::: "memory");
        asm volatile("tcgen05.fence::before_thread_sync;" ::: "memory");

        int m = bm + (tid >> 5) * 32 + (tid & 31);
        float* Crow = C + (long long)m * ldc + bn;
        const float* Rrow = (EPI == 2) ? (resid + (long long)m * ldr + bn) : nullptr;
        #pragma unroll
        for (int c4 = 0; c4 < 16; c4++) {
            float vv[4];
            #pragma unroll
            for (int j = 0; j < 4; j++) {
                int c = c4 * 4 + j;
                float v = __uint_as_float(dr[c]) * alpha;
                if (EPI >= 1) v += bias[bn + c];
                if (EPI == 2) v += Rrow[c];
                if (EPI == 3) v = 0.5f * v * (1.0f + erff(v * 0.70710678118654752f));
                vv[j] = v;
            }
            float4 o = {vv[0], vv[1], vv[2], vv[3]};
            *(float4*)(Crow + c4 * 4) = o;
        }
    }
    __syncthreads();
    if (tid == 0) mbar_inval(bar);
    if (wid == 0) {
        asm volatile("tcgen05.dealloc.cta_group::1.sync.aligned.b32 %0, %1;"
                     :: "r"(tmem), "r"(64u));
    }
#else
    // FFMA fallback: reconstruct fp32 from planes
    float* As = (float*)smem;          // [16][128]
    float* Bs = As + 16 * 128;         // [16][64]
    const int tx = tid & 15, ty = tid >> 4;
    float acc[8][4];
    #pragma unroll
    for (int i = 0; i < 8; i++)
        #pragma unroll
        for (int j = 0; j < 4; j++) acc[i][j] = 0.f;
    for (int k0 = 0; k0 < K; k0 += 16) {
        {
            int row = tid >> 1, col = (tid & 1) * 8;
            long long g = (long long)(bm + row) * lda + k0 + col;
            #pragma unroll
            for (int i = 0; i < 8; i++)
                As[(col + i) * 128 + row] = rec3(Ah, Am, Al, g + i);
        }
        {
            int nn = tid >> 2, kk = (tid & 3) * 4;
            long long g = (long long)(bn + nn) * ldb + k0 + kk;
            #pragma unroll
            for (int j = 0; j < 4; j++)
                Bs[(kk + j) * 64 + nn] = rec3(Bh, Bm, Bl, g + j);
        }
        __syncthreads();
        #pragma unroll
        for (int kk = 0; kk < 16; kk++) {
            float a[8], b[4];
            #pragma unroll
            for (int i = 0; i < 8; i++) a[i] = As[kk * 128 + ty * 8 + i];
            #pragma unroll
            for (int j = 0; j < 4; j++) b[j] = Bs[kk * 64 + tx * 4 + j];
            #pragma unroll
            for (int i = 0; i < 8; i++)
                #pragma unroll
                for (int j = 0; j < 4; j++) acc[i][j] = fmaf(a[i], b[j], acc[i][j]);
        }
        __syncthreads();
    }
    #pragma unroll
    for (int i = 0; i < 8; i++) {
        int gm = bm + ty * 8 + i;
        #pragma unroll
        for (int j = 0; j < 4; j++) {
            int gn = bn + tx * 4 + j;
            float v = acc[i][j] * alpha;
            if (EPI >= 1) v += bias[gn];
            if (EPI == 2) v += resid[(long long)gm * ldr + gn];
            if (EPI == 3) v = 0.5f * v * (1.0f + erff(v * 0.70710678118654752f));
            C[(long long)gm * ldc + gn] = v;
        }
    }
#endif
}

// ---------------- split (no transpose): fp32 -> 3 bf16 planes ----------------
__global__ void split_kernel(const float* __restrict__ in, bf16* __restrict__ ph,
                             bf16* __restrict__ pm, bf16* __restrict__ pl, long long n4)
{
    long long stride = (long long)gridDim.x * blockDim.x;
    for (long long i = (long long)blockIdx.x * blockDim.x + threadIdx.x; i < n4; i += stride) {
        float4 v = ((const float4*)in)[i];
        bf16 h[4], m[4], l[4];
        split3(v.x, h[0], m[0], l[0]);
        split3(v.y, h[1], m[1], l[1]);
        split3(v.z, h[2], m[2], l[2]);
        split3(v.w, h[3], m[3], l[3]);
        ((uint2*)ph)[i] = make_uint2(pk2(h[0], h[1]), pk2(h[2], h[3]));
        ((uint2*)pm)[i] = make_uint2(pk2(m[0], m[1]), pk2(m[2], m[3]));
        ((uint2*)pl)[i] = make_uint2(pk2(l[0], l[1]), pk2(l[2], l[3]));
    }
}

// ---------------- transpose + split: in[z][r][c] -> planes[z][c][r] ----------------
__global__ void splitT_kernel(const float* __restrict__ in, int ldi,
                              long long sInO, long long sInI, int zdiv,
                              bf16* __restrict__ ph, bf16* __restrict__ pm,
                              bf16* __restrict__ pl, int ldo, long long sOut)
{
    __shared__ float t[32][33];
    int z = blockIdx.z;
    int zo = z / zdiv, zi = z - zo * zdiv;
    const float* ib = in + zo * sInO + zi * sInI;
    int c0 = blockIdx.x * 32, r0 = blockIdx.y * 32;
    for (int i = threadIdx.y; i < 32; i += 8)
        t[i][threadIdx.x] = ib[(long long)(r0 + i) * ldi + c0 + threadIdx.x];
    __syncthreads();
    long long ob = (long long)z * sOut;
    for (int i = threadIdx.y; i < 32; i += 8) {
        int c = c0 + i, r = r0 + threadIdx.x;
        long long o = ob + (long long)c * ldo + r;
        split3(t[threadIdx.x][i], ph[o], pm[o], pl[o]);
    }
}

// ---------------- embedding + LN (fp32 + planes) ----------------
__global__ void embed_ln_kernel(const int* __restrict__ ids, const int* __restrict__ tts,
                                const float* __restrict__ we, const float* __restrict__ pe,
                                const float* __restrict__ te, const float* __restrict__ s,
                                const float* __restrict__ b, float* __restrict__ out,
                                bf16* __restrict__ ph, bf16* __restrict__ pm,
                                bf16* __restrict__ pl)
{
    int n = blockIdx.x;
    int sp = n & (SEQL - 1);
    int id = ids[n];
    int tt = tts[n];
    float v[3];
    float sum = 0.f;
    #pragma unroll
    for (int i = 0; i < 3; i++) {
        int h = threadIdx.x + i * 256;
        v[i] = we[(long long)id * HDIM + h] + pe[sp * HDIM + h] + te[tt * HDIM + h];
        sum += v[i];
    }
    float mean = blockReduceSum(sum) * (1.f / HDIM);
    float vs = 0.f;
    #pragma unroll
    for (int i = 0; i < 3; i++) { float d = v[i] - mean; vs += d * d; }
    float var = blockReduceSum(vs) * (1.f / HDIM);
    float inv = rsqrtf(var + 1e-12f);
    #pragma unroll
    for (int i = 0; i < 3; i++) {
        int h = threadIdx.x + i * 256;
        float y = (v[i] - mean) * inv * s[h] + b[h];
        long long o = (long long)n * HDIM + h;
        out[o] = y;
        split3(y, ph[o], pm[o], pl[o]);
    }
}

// ---------------- LN (fp32 + planes out) ----------------
__global__ void layernorm_kernel(const float* __restrict__ in, float* __restrict__ out,
                                 bf16* __restrict__ ph, bf16* __restrict__ pm,
                                 bf16* __restrict__ pl,
                                 const float* __restrict__ s, const float* __restrict__ b)
{
    int n = blockIdx.x;
    const float* row = in + (long long)n * HDIM;
    float v[3];
    float sum = 0.f;
    #pragma unroll
    for (int i = 0; i < 3; i++) { v[i] = row[threadIdx.x + i * 256]; sum += v[i]; }
    float mean = blockReduceSum(sum) * (1.f / HDIM);
    float vs = 0.f;
    #pragma unroll
    for (int i = 0; i < 3; i++) { float d = v[i] - mean; vs += d * d; }
    float var = blockReduceSum(vs) * (1.f / HDIM);
    float inv = rsqrtf(var + 1e-12f);
    #pragma unroll
    for (int i = 0; i < 3; i++) {
        int h = threadIdx.x + i * 256;
        float y = (v[i] - mean) * inv * s[h] + b[h];
        long long o = (long long)n * HDIM + h;
        out[o] = y;
        split3(y, ph[o], pm[o], pl[o]);
    }
}

// ---------------- masked softmax (fp32 in -> planes out) ----------------
__global__ void softmax_kernel(const float* __restrict__ sc, const int* __restrict__ amask,
                               bf16* __restrict__ ph, bf16* __restrict__ pm,
                               bf16* __restrict__ pl)
{
    int q = blockIdx.x;
    int bh = blockIdx.y;
    int b = bh / NHEAD;
    long long rowo = ((long long)bh * SEQL + q) * SEQL;
    const float* row = sc + rowo;
    const int* mrow = amask + b * SEQL;
    int t = threadIdx.x;
    float v[4];
    float mx = -1e30f;
    #pragma unroll
    for (int i = 0; i < 4; i++) {
        int k = t + i * 128;
        float bias = (mrow[k] > 0) ? 0.f : -10000.f;
        v[i] = row[k] + bias;
        mx = fmaxf(mx, v[i]);
    }
    __shared__ float shm[4];
    #pragma unroll
    for (int o = 16; o > 0; o >>= 1) mx = fmaxf(mx, __shfl_xor_sync(0xffffffffu, mx, o));
    if ((t & 31) == 0) shm[t >> 5] = mx;
    __syncthreads();
    mx = fmaxf(fmaxf(shm[0], shm[1]), fmaxf(shm[2], shm[3]));
    float s = 0.f;
    #pragma unroll
    for (int i = 0; i < 4; i++) { v[i] = __expf(v[i] - mx); s += v[i]; }
    #pragma unroll
    for (int o = 16; o > 0; o >>= 1) s += __shfl_xor_sync(0xffffffffu, s, o);
    __shared__ float shs[4];
    if ((t & 31) == 0) shs[t >> 5] = s;
    __syncthreads();
    s = shs[0] + shs[1] + shs[2] + shs[3];
    float inv = 1.f / s;
    #pragma unroll
    for (int i = 0; i < 4; i++) {
        long long o = rowo + t + i * 128;
        split3(v[i] * inv, ph[o], pm[o], pl[o]);
    }
}

// ---------------- classifier (N=9, FFMA) ----------------
__global__ __launch_bounds__(256)
void clf_gemm(const float* __restrict__ A, const float* __restrict__ B,
              const float* __restrict__ bias, float* __restrict__ C)
{
    __shared__ float As[16][128];
    __shared__ float Bs[16][NLAB];
    int bm = blockIdx.y * 128;
    int tid = threadIdx.x;
    int tx = tid & 15, ty = tid >> 4;
    float acc[8][4];
    #pragma unroll
    for (int i = 0; i < 8; i++)
        #pragma unroll
        for (int j = 0; j < 4; j++) acc[i][j] = 0.f;
    for (int k0 = 0; k0 < HDIM; k0 += 16) {
        {
            int row = tid >> 1, col = (tid & 1) * 8;
            #pragma unroll
            for (int i = 0; i < 8; i++)
                As[col + i][row] = A[(long long)(bm + row) * HDIM + k0 + col + i];
        }
        if (tid < 16) {
            #pragma unroll
            for (int j = 0; j < NLAB; j++)
                Bs[tid][j] = B[(long long)(k0 + tid) * NLAB + j];
        }
        __syncthreads();
        #pragma unroll
        for (int kk = 0; kk < 16; kk++) {
            float a[8];
            #pragma unroll
            for (int i = 0; i < 8; i++) a[i] = As[kk][ty * 8 + i];
            #pragma unroll
            for (int j = 0; j < 4; j++) {
                int gn = tx * 4 + j;
                float bv = (gn < NLAB) ? Bs[kk][gn] : 0.f;
                #pragma unroll
                for (int i = 0; i < 8; i++) acc[i][j] = fmaf(a[i], bv, acc[i][j]);
            }
        }
        __syncthreads();
    }
    #pragma unroll
    for (int i = 0; i < 8; i++) {
        int gm = bm + ty * 8 + i;
        #pragma unroll
        for (int j = 0; j < 4; j++) {
            int gn = tx * 4 + j;
            if (gn < NLAB) C[(long long)gm * NLAB + gn] = acc[i][j] + bias[gn];
        }
    }
}

// ---------------- CRF loss ----------------
__global__ void crf_loss_kernel(const float* __restrict__ feats, const int* __restrict__ labels,
                                const int* __restrict__ amask, const float* __restrict__ start,
                                const float* __restrict__ endv, const float* __restrict__ trans,
                                float* __restrict__ part)
{
    int w = threadIdx.x >> 5;
    int lane = threadIdx.x & 31;
    int j = (lane < NLAB) ? lane : NLAB - 1;
    const float* em = feats + (long long)w * SEQL * NLAB;
    const int* mk = amask + w * SEQL;
    float tr[NLAB];
    #pragma unroll
    for (int i = 0; i < NLAB; i++) tr[i] = trans[i * NLAB + j];
    float score = start[j] + em[j];
    for (int t = 1; t < SEQL; t++) {
        float c[NLAB];
        float m = -1e30f;
        #pragma unroll
        for (int i = 0; i < NLAB; i++) {
            c[i] = __shfl_sync(0xffffffffu, score, i) + tr[i];
            m = fmaxf(m, c[i]);
        }
        float s = 0.f;
        #pragma unroll
        for (int i = 0; i < NLAB; i++) s += __expf(c[i] - m);
        float nxt = m + __logf(s) + em[t * NLAB + j];
        score = (mk[t] > 0) ? nxt : score;
    }
    float fin = (lane < NLAB) ? score + endv[j] : -1e30f;
    float m = fin;
    #pragma unroll
    for (int o = 16; o > 0; o >>= 1) m = fmaxf(m, __shfl_xor_sync(0xffffffffu, m, o));
    float s = (lane < NLAB) ? __expf(fin - m) : 0.f;
    #pragma unroll
    for (int o = 16; o > 0; o >>= 1) s += __shfl_xor_sync(0xffffffffu, s, o);
    float logZ = m + __logf(s);
    if (lane == 0) {
        const int* tg = labels + w * SEQL;
        float num = start[tg[0]] + em[tg[0]];
        int cnt = (mk[0] > 0) ? 1 : 0;
        for (int t = 1; t < SEQL; t++) {
            float mf = (float)mk[t];
            num += (em[t * NLAB + tg[t]] + trans[tg[t - 1] * NLAB + tg[t]]) * mf;
            cnt += (mk[t] > 0) ? 1 : 0;
        }
        int last = cnt - 1;
        num += endv[tg[last]];
        part[w] = logZ - num;
    }
}

// ---------------- Viterbi ----------------
__global__ void viterbi_kernel(const float* __restrict__ feats, const int* __restrict__ amask,
                               const float* __restrict__ start, const float* __restrict__ endv,
                               const float* __restrict__ trans, int* __restrict__ hist,
                               int* __restrict__ tags)
{
    int w = threadIdx.x >> 5;
    int lane = threadIdx.x & 31;
    int j = (lane < NLAB) ? lane : NLAB - 1;
    const float* em = feats + (long long)w * SEQL * NLAB;
    const int* mk = amask + w * SEQL;
    float tr[NLAB];
    #pragma unroll
    for (int i = 0; i < NLAB; i++) tr[i] = trans[i * NLAB + j];
    float score = start[j] + em[j];
    for (int t = 1; t < SEQL; t++) {
        float best = -1e30f;
        int bi = 0;
        #pragma unroll
        for (int i = 0; i < NLAB; i++) {
            float c = __shfl_sync(0xffffffffu, score, i) + tr[i];
            if (c > best) { best = c; bi = i; }
        }
        if (lane < NLAB) hist[((t - 1) * NB + w) * NLAB + j] = bi;
        float nxt = best + em[t * NLAB + j];
        score = (mk[t] > 0) ? nxt : score;
    }
    float fin = score + endv[j];
    int last = 0;
    float bm = -1e30f;
    #pragma unroll
    for (int i = 0; i < NLAB; i++) {
        float c = __shfl_sync(0xffffffffu, fin, i);
        if (c > bm) { bm = c; last = i; }
    }
    if (lane == 0) {
        int tag = last;
        tags[w * SEQL + SEQL - 1] = tag;
        for (int t = SEQL - 2; t >= 0; t--) {
            tag = hist[(t * NB + w) * NLAB + tag];
            tags[w * SEQL + t] = tag;
        }
    }
}

__global__ void finalize_kernel(const float* __restrict__ part, const int* __restrict__ tags,
                                float* __restrict__ out, int out_size)
{
    if (threadIdx.x == 0 && out_size > 0) {
        float s = 0.f;
        #pragma unroll
        for (int w = 0; w < NB; w++) s += part[w];
        out[0] = s * (1.f / NB);
    }
    for (int i = threadIdx.x; i < NB * SEQL; i += blockDim.x) {
        if (1 + i < out_size) out[1 + i] = (float)tags[i];
    }
}

// ---------------- host ----------------
#define P3(p, n) p, (p) + (n), (p) + 2 * (n)

extern "C" void kernel_launch(void* const* d_in, const int* in_sizes, int n_in,
                              void* d_out, int out_size)
{
    const float* word_emb  = (const float*)d_in[0];
    const float* pos_emb   = (const float*)d_in[1];
    const float* type_emb  = (const float*)d_in[2];
    const float* emb_ln_s  = (const float*)d_in[3];
    const float* emb_ln_b  = (const float*)d_in[4];
    const float* Wq        = (const float*)d_in[5];
    const float* bq        = (const float*)d_in[6];
    const float* Wk        = (const float*)d_in[7];
    const float* bk        = (const float*)d_in[8];
    const float* Wv        = (const float*)d_in[9];
    const float* bv        = (const float*)d_in[10];
    const float* Wo        = (const float*)d_in[11];
    const float* bo        = (const float*)d_in[12];
    const float* ln1_s     = (const float*)d_in[13];
    const float* ln1_b     = (const float*)d_in[14];
    const float* W1        = (const float*)d_in[15];
    const float* b1        = (const float*)d_in[16];
    const float* W2        = (const float*)d_in[17];
    const float* b2        = (const float*)d_in[18];
    const float* ln2_s     = (const float*)d_in[19];
    const float* ln2_b     = (const float*)d_in[20];
    const float* clf_W     = (const float*)d_in[21];
    const float* clf_b     = (const float*)d_in[22];
    const float* crf_start = (const float*)d_in[23];
    const float* crf_end   = (const float*)d_in[24];
    const float* crf_trans = (const float*)d_in[25];
    const int*   input_ids = (const int*)d_in[26];
    const int*   tok_types = (const int*)d_in[27];
    const int*   amask     = (const int*)d_in[28];
    const int*   labels    = (const int*)d_in[29];
    (void)in_sizes; (void)n_in;

    float *X, *T, *Q, *Kb, *V, *Ctx, *H1, *FFb, *Sc, *Feats, *Part;
    int *Hist, *Tags;
    cudaGetSymbolAddress((void**)&X,   gX);
    cudaGetSymbolAddress((void**)&T,   gT);
    cudaGetSymbolAddress((void**)&Q,   gQ);
    cudaGetSymbolAddress((void**)&Kb,  gK);
    cudaGetSymbolAddress((void**)&V,   gV);
    cudaGetSymbolAddress((void**)&Ctx, gCtx);
    cudaGetSymbolAddress((void**)&H1,  gH1);
    cudaGetSymbolAddress((void**)&FFb, gFF);
    cudaGetSymbolAddress((void**)&Sc,  gSc);
    cudaGetSymbolAddress((void**)&Feats, gFeats);
    cudaGetSymbolAddress((void**)&Part,  gPart);
    cudaGetSymbolAddress((void**)&Hist,  gHist);
    cudaGetSymbolAddress((void**)&Tags,  gTags);

    bf16 *pX, *pQ, *pK, *pC, *pH, *pF, *pP, *pV;
    bf16 *qW, *kW, *vW, *oW, *w1p, *w2p;
    cudaGetSymbolAddress((void**)&pX, aX);
    cudaGetSymbolAddress((void**)&pQ, aQ);
    cudaGetSymbolAddress((void**)&pK, aK);
    cudaGetSymbolAddress((void**)&pC, aCtx);
    cudaGetSymbolAddress((void**)&pH, aH1);
    cudaGetSymbolAddress((void**)&pF, aFF);
    cudaGetSymbolAddress((void**)&pP, aP);
    cudaGetSymbolAddress((void**)&pV, aVt);
    cudaGetSymbolAddress((void**)&qW, wQt);
    cudaGetSymbolAddress((void**)&kW, wKt);
    cudaGetSymbolAddress((void**)&vW, wVt);
    cudaGetSymbolAddress((void**)&oW, wOt);
    cudaGetSymbolAddress((void**)&w1p, w1t);
    cudaGetSymbolAddress((void**)&w2p, w2t);

    cudaFuncSetAttribute(tc_gemm3<0>, cudaFuncAttributeMaxDynamicSharedMemorySize, SM_TOTAL);
    cudaFuncSetAttribute(tc_gemm3<1>, cudaFuncAttributeMaxDynamicSharedMemorySize, SM_TOTAL);
    cudaFuncSetAttribute(tc_gemm3<2>, cudaFuncAttributeMaxDynamicSharedMemorySize, SM_TOTAL);
    cudaFuncSetAttribute(tc_gemm3<3>, cudaFuncAttributeMaxDynamicSharedMemorySize, SM_TOTAL);

    embed_ln_kernel<<<MROWS, 256>>>(input_ids, tok_types, word_emb, pos_emb, type_emb,
                                    emb_ln_s, emb_ln_b, X, P3(pX, NXH));

    dim3 tb(32, 8);
    dim3 gQKV(HDIM / 64, MROWS / 128);                  // 12 x 32
    dim3 gScore(SEQL / 64, SEQL / 128, NBH);            // 8 x 4 x 96
    dim3 gCtxG(1, SEQL / 128, NBH);                     // 1 x 4 x 96
    dim3 gFF1(FFDIM / 64, MROWS / 128);                 // 48 x 32
    dim3 gClf(1, MROWS / 128);
    int sXH = (int)(NXH / 4 + 255) / 256;
    int sFF = (int)(NFF / 4 + 255) / 256;

    for (int l = 0; l < NLAYR; l++) {
        const float* Wq_l = Wq + l * NHH;
        const float* Wk_l = Wk + l * NHH;
        const float* Wv_l = Wv + l * NHH;
        const float* Wo_l = Wo + l * NHH;
        const float* W1_l = W1 + l * NHF;
        const float* W2_l = W2 + l * NHF;

        // transpose-split weights: W[K][N] -> planes [N][K]
        splitT_kernel<<<dim3(24, 24, 1), tb>>>(Wq_l, HDIM, 0, 0, 1, P3(qW, NHH), HDIM, 0);
        splitT_kernel<<<dim3(24, 24, 1), tb>>>(Wk_l, HDIM, 0, 0, 1, P3(kW, NHH), HDIM, 0);
        splitT_kernel<<<dim3(24, 24, 1), tb>>>(Wv_l, HDIM, 0, 0, 1, P3(vW, NHH), HDIM, 0);
        splitT_kernel<<<dim3(24, 24, 1), tb>>>(Wo_l, HDIM, 0, 0, 1, P3(oW, NHH), HDIM, 0);
        splitT_kernel<<<dim3(96, 24, 1), tb>>>(W1_l, FFDIM, 0, 0, 1, P3(w1p, NHF), HDIM, 0);
        splitT_kernel<<<dim3(24, 96, 1), tb>>>(W2_l, HDIM, 0, 0, 1, P3(w2p, NHF), FFDIM, 0);

        // Q, K, V projections
        tc_gemm3<1><<<gQKV, 256, SM_TOTAL>>>(P3(pX, NXH), HDIM, 0, 0, P3(qW, NHH), HDIM, 0, 0,
            Q, HDIM, 0, 0, bq + l * HDIM, nullptr, 0, MROWS, HDIM, HDIM, 1.f, 1);
        tc_gemm3<1><<<gQKV, 256, SM_TOTAL>>>(P3(pX, NXH), HDIM, 0, 0, P3(kW, NHH), HDIM, 0, 0,
            Kb, HDIM, 0, 0, bk + l * HDIM, nullptr, 0, MROWS, HDIM, HDIM, 1.f, 1);
        tc_gemm3<1><<<gQKV, 256, SM_TOTAL>>>(P3(pX, NXH), HDIM, 0, 0, P3(vW, NHH), HDIM, 0, 0,
            V, HDIM, 0, 0, bv + l * HDIM, nullptr, 0, MROWS, HDIM, HDIM, 1.f, 1);
        split_kernel<<<sXH, 256>>>(Q, P3(pQ, NXH), NXH / 4);
        split_kernel<<<sXH, 256>>>(Kb, P3(pK, NXH), NXH / 4);
        // V per-head transpose: [b*512+s][h*64+d] -> Vt[bh][d][s]
        splitT_kernel<<<dim3(2, 16, NBH), tb>>>(V, HDIM, SH, DHEAD, NHEAD,
            P3(pV, NVT), SEQL, (long long)DHEAD * SEQL);

        // scores = 0.125 * Q K^T
        tc_gemm3<0><<<gScore, 256, SM_TOTAL>>>(P3(pQ, NXH), HDIM, SH, DHEAD,
            P3(pK, NXH), HDIM, SH, DHEAD,
            Sc, SEQL, (long long)NHEAD * SS, SS, nullptr, nullptr, 0,
            SEQL, SEQL, DHEAD, 0.125f, NHEAD);

        softmax_kernel<<<dim3(SEQL, NBH), 128>>>(Sc, amask, P3(pP, NPP));

        // ctx = P @ V^T(planes)
        tc_gemm3<0><<<gCtxG, 256, SM_TOTAL>>>(P3(pP, NPP), SEQL, (long long)NHEAD * SS, SS,
            P3(pV, NVT), SEQL, (long long)NHEAD * DHEAD * SEQL, (long long)DHEAD * SEQL,
            Ctx, HDIM, SH, DHEAD, nullptr, nullptr, 0,
            SEQL, DHEAD, SEQL, 1.f, NHEAD);
        split_kernel<<<sXH, 256>>>(Ctx, P3(pC, NXH), NXH / 4);

        // attn out + residual -> T, LN1 -> H1 (+planes)
        tc_gemm3<2><<<gQKV, 256, SM_TOTAL>>>(P3(pC, NXH), HDIM, 0, 0, P3(oW, NHH), HDIM, 0, 0,
            T, HDIM, 0, 0, bo + l * HDIM, X, HDIM, MROWS, HDIM, HDIM, 1.f, 1);
        layernorm_kernel<<<MROWS, 256>>>(T, H1, P3(pH, NXH),
                                         ln1_s + l * HDIM, ln1_b + l * HDIM);

        // FF1 + GELU -> FFb, split
        tc_gemm3<3><<<gFF1, 256, SM_TOTAL>>>(P3(pH, NXH), HDIM, 0, 0, P3(w1p, NHF), HDIM, 0, 0,
            FFb, FFDIM, 0, 0, b1 + l * FFDIM, nullptr, 0, MROWS, FFDIM, HDIM, 1.f, 1);
        split_kernel<<<sFF, 256>>>(FFb, P3(pF, NFF), NFF / 4);

        // FF2 + residual -> T, LN2 -> X (+planes)
        tc_gemm3<2><<<gQKV, 256, SM_TOTAL>>>(P3(pF, NFF), FFDIM, 0, 0, P3(w2p, NHF), FFDIM, 0, 0,
            T, HDIM, 0, 0, b2 + l * HDIM, H1, HDIM, MROWS, HDIM, FFDIM, 1.f, 1);
        layernorm_kernel<<<MROWS, 256>>>(T, X, P3(pX, NXH),
                                         ln2_s + l * HDIM, ln2_b + l * HDIM);
    }

    clf_gemm<<<gClf, 256>>>(X, clf_W, clf_b, Feats);
    crf_loss_kernel<<<1, 256>>>(Feats, labels, amask, crf_start, crf_end, crf_trans, Part);
    viterbi_kernel<<<1, 256>>>(Feats, amask, crf_start, crf_end, crf_trans, Hist, Tags);
    finalize_kernel<<<1, 512>>>(Part, Tags, (float*)d_out, out_size);
}